// round 12
// baseline (speedup 1.0000x reference)
#include <cuda_runtime.h>
#include <stdint.h>

// ---------------- static scratch (no runtime alloc allowed) ----------------
#define MAXN 100000
#define MAXE 3200000

__device__ __align__(16) float g_c1out[MAXN * 64];          // [N, 64]  xl_c1 | xr_c1
__device__ __align__(16) float g_h1[MAXN * 32];             // [N, 32]
__device__ __align__(16) float g_c2out[(size_t)MAXN * 256]; // [N,256] xl_c2 | xr_c2
__device__ __align__(16) float g_h2[MAXN * 128];            // [N,128]
__device__ __align__(16) float g_c3out[MAXN * 128];         // [N,128] mu_l|mu_r|ls_l|ls_r
__device__ __align__(16) float g_Wpack[512 * 64];           // packed weights (reused)
__device__ int g_counts[MAXN];
__device__ int g_fill[MAXN];
__device__ int g_rowptr[MAXN + 1];
__device__ int g_srcs[MAXE];
__device__ int g_blockSums[256];
__device__ int g_isI64;

// ---------------- helpers ----------------
__device__ __forceinline__ float warpSum(float v) {
#pragma unroll
    for (int o = 16; o > 0; o >>= 1) v += __shfl_xor_sync(0xffffffffu, v, o);
    return v;
}

__device__ __forceinline__ float lk(float v) { return v > 0.f ? v : 0.2f * v; }

// packed fp32x2 FMA (sm_103a FFMA2) — IEEE fp32 per lane
__device__ __forceinline__ unsigned long long ffma2(unsigned long long a,
                                                    unsigned long long b,
                                                    unsigned long long c) {
    unsigned long long d;
    asm("fma.rn.f32x2 %0, %1, %2, %3;" : "=l"(d) : "l"(a), "l"(b), "l"(c));
    return d;
}
__device__ __forceinline__ unsigned long long pack2(float lo, float hi) {
    unsigned long long r;
    asm("mov.b64 %0, {%1, %2};" : "=l"(r) : "f"(lo), "f"(hi));
    return r;
}
__device__ __forceinline__ void unpack2(unsigned long long v, float& lo, float& hi) {
    asm("mov.b64 {%0, %1}, %2;" : "=f"(lo), "=f"(hi) : "l"(v));
}

// dtype-aware edge-index accessor (int32 vs int64 decided at runtime on device)
__device__ __forceinline__ int edgeIdx(const void* p, long long i) {
    if (g_isI64) return (int)((const long long*)p)[i];
    return ((const int*)p)[i];
}

// ---------------- dtype probe ----------------
__global__ void k_probe(const unsigned int* __restrict__ w) {
    if (threadIdx.x == 0 && blockIdx.x == 0) {
        int allz = 1;
        for (int i = 0; i < 32; i++) allz &= (w[2 * i + 1] == 0u);
        g_isI64 = allz;
    }
}

// ---------------- CSR build ----------------
__global__ void k_zero2(int n) {
    int i = blockIdx.x * blockDim.x + threadIdx.x;
    if (i < n) { g_counts[i] = 0; g_fill[i] = 0; }
}

__global__ void k_hist(const void* __restrict__ ei, int E, int N) {
    int e = blockIdx.x * blockDim.x + threadIdx.x;
    if (e < E) {
        int d = edgeIdx(ei, (long long)E + e);
        if ((unsigned)d < (unsigned)N) atomicAdd(&g_counts[d], 1);
    }
}

__global__ void k_scan1(int n) {  // block=1024
    __shared__ int sm[1024];
    int tid = threadIdx.x;
    int i = blockIdx.x * 1024 + tid;
    int v = (i < n) ? g_counts[i] : 0;
    sm[tid] = v;
    __syncthreads();
#pragma unroll
    for (int off = 1; off < 1024; off <<= 1) {
        int add = (tid >= off) ? sm[tid - off] : 0;
        __syncthreads();
        sm[tid] += add;
        __syncthreads();
    }
    if (i < n) g_rowptr[i] = sm[tid] - v;
    if (tid == 1023) g_blockSums[blockIdx.x] = sm[1023];
}

__global__ void k_scan2(int nb) {
    if (threadIdx.x == 0 && blockIdx.x == 0) {
        int run = 0;
        for (int b = 0; b < nb; b++) { int t = g_blockSums[b]; g_blockSums[b] = run; run += t; }
    }
}

__global__ void k_scan3(int n, int E) {
    int i = blockIdx.x * blockDim.x + threadIdx.x;
    if (i < n) g_rowptr[i] += g_blockSums[i >> 10];
    if (i == 0) g_rowptr[n] = E;
}

__global__ void k_scatter(const void* __restrict__ ei, int E, int N) {
    int e = blockIdx.x * blockDim.x + threadIdx.x;
    if (e < E) {
        int d = edgeIdx(ei, (long long)E + e);
        int s = edgeIdx(ei, e);
        if ((unsigned)d < (unsigned)N && (unsigned)s < (unsigned)N) {
            int p = g_rowptr[d] + atomicAdd(&g_fill[d], 1);
            g_srcs[p] = s;
        }
    }
}

// ---------------- weight packing ----------------
__global__ void k_pack2(const float* __restrict__ Wl, const float* __restrict__ Wr,
                        int K, int D) {
    int i = blockIdx.x * blockDim.x + threadIdx.x;
    if (i >= K * D) return;
    int k = i / D, d = i % D;
    g_Wpack[k * 2 * D + d]     = Wl[i];
    g_Wpack[k * 2 * D + D + d] = Wr[i];
}

__global__ void k_pack4(const float* __restrict__ W0, const float* __restrict__ W1,
                        const float* __restrict__ W2, const float* __restrict__ W3,
                        int K) {
    int i = blockIdx.x * blockDim.x + threadIdx.x;
    if (i >= K * 32) return;
    int k = i / 32, d = i % 32;
    g_Wpack[k * 128 + d]       = W0[i];
    g_Wpack[k * 128 + 32 + d]  = W1[i];
    g_Wpack[k * 128 + 64 + d]  = W2[i];
    g_Wpack[k * 128 + 96 + d]  = W3[i];
}

// ---------------- SGEMM (FFMA2, 4x8 thread tile): C[M,Nn] = A[M,K] @ g_Wpack ----------------
// BM=128 BN=64 BK=16, 256 threads. Thread tile: 4 rows (2 f32x2 pairs) x 8 cols.
// Per k-step: 2x LDS.64 (A) + 2x LDS.128 (B) feeding 16 FFMA2 (was 8 LDS in R10).
template <int LAYER>
__global__ __launch_bounds__(256) void k_sgemm(const float* __restrict__ Aext,
                                               int M, int Nn, int K) {
    const float* __restrict__ A = (LAYER == 0) ? Aext : (LAYER == 1 ? g_h1 : g_h2);
    float* __restrict__ C = (LAYER == 0) ? g_c1out : (LAYER == 1 ? g_c2out : g_c3out);
    const float* __restrict__ B = g_Wpack;

    __shared__ float As[16][128];
    __shared__ float Bs[16][64];
    const int rowBase = blockIdx.x * 128;
    const int colBase = blockIdx.y * 64;
    const int t = threadIdx.x;
    const int tx = t & 7;    // col group: 8 cols
    const int ty = t >> 3;   // row group: 4 rows (0..31)
    unsigned long long acc2[2][8];  // [rowpair][col]
#pragma unroll
    for (int i = 0; i < 2; i++)
#pragma unroll
        for (int j = 0; j < 8; j++) acc2[i][j] = 0ull;

    for (int k0 = 0; k0 < K; k0 += 16) {
#pragma unroll
        for (int i = 0; i < 2; i++) {
            int f = t + i * 256;
            int r = f >> 2, c4 = f & 3;
            int grow = rowBase + r;
            float4 v = make_float4(0.f, 0.f, 0.f, 0.f);
            if (grow < M)
                v = *reinterpret_cast<const float4*>(A + (size_t)grow * K + k0 + c4 * 4);
            As[c4 * 4 + 0][r] = v.x;
            As[c4 * 4 + 1][r] = v.y;
            As[c4 * 4 + 2][r] = v.z;
            As[c4 * 4 + 3][r] = v.w;
        }
        {
            int kk = t >> 4, c4 = t & 15;
            float4 v = *reinterpret_cast<const float4*>(B + (size_t)(k0 + kk) * Nn + colBase + c4 * 4);
            *reinterpret_cast<float4*>(&Bs[kk][c4 * 4]) = v;
        }
        __syncthreads();
#pragma unroll
        for (int k = 0; k < 16; k++) {
            unsigned long long a2[2];
            a2[0] = *reinterpret_cast<const unsigned long long*>(&As[k][ty * 4]);
            a2[1] = *reinterpret_cast<const unsigned long long*>(&As[k][ty * 4 + 2]);
            float4 b0 = *reinterpret_cast<const float4*>(&Bs[k][tx * 8]);
            float4 b1 = *reinterpret_cast<const float4*>(&Bs[k][tx * 8 + 4]);
            unsigned long long bd[8];
            bd[0] = pack2(b0.x, b0.x); bd[1] = pack2(b0.y, b0.y);
            bd[2] = pack2(b0.z, b0.z); bd[3] = pack2(b0.w, b0.w);
            bd[4] = pack2(b1.x, b1.x); bd[5] = pack2(b1.y, b1.y);
            bd[6] = pack2(b1.z, b1.z); bd[7] = pack2(b1.w, b1.w);
#pragma unroll
            for (int i = 0; i < 2; i++)
#pragma unroll
                for (int j = 0; j < 8; j++) acc2[i][j] = ffma2(a2[i], bd[j], acc2[i][j]);
        }
        __syncthreads();
    }
    // epilogue: 4 rows x 8 cols per thread
#pragma unroll
    for (int i = 0; i < 2; i++) {
        float lo[8], hi[8];
#pragma unroll
        for (int j = 0; j < 8; j++) unpack2(acc2[i][j], lo[j], hi[j]);
        int r0 = rowBase + ty * 4 + i * 2;
        if (r0 < M) {
            float* cp = C + (size_t)r0 * Nn + colBase + tx * 8;
            *reinterpret_cast<float4*>(cp)     = make_float4(lo[0], lo[1], lo[2], lo[3]);
            *reinterpret_cast<float4*>(cp + 4) = make_float4(lo[4], lo[5], lo[6], lo[7]);
        }
        if (r0 + 1 < M) {
            float* cp = C + (size_t)(r0 + 1) * Nn + colBase + tx * 8;
            *reinterpret_cast<float4*>(cp)     = make_float4(hi[0], hi[1], hi[2], hi[3]);
            *reinterpret_cast<float4*>(cp + 4) = make_float4(hi[4], hi[5], hi[6], hi[7]);
        }
    }
}

// ---------------- GATv2 edge kernels (4-edge unroll online softmax — R11) ----------------
__global__ void k_gat32(const float* __restrict__ att, const float* __restrict__ bias, int N) {
    int warp = (blockIdx.x * blockDim.x + threadIdx.x) >> 5;
    int lane = threadIdx.x & 31;
    if (warp >= N) return;
    float attk = att[lane];
    float bk = bias[lane];
    const float* xin = g_c1out;
    float xrk = xin[(size_t)warp * 64 + 32 + lane];
    float xlk0 = xin[(size_t)warp * 64 + lane];
    float m = warpSum(lk(xlk0 + xrk) * attk);
    float ssum = 1.f, acc = xlk0;
    int beg = g_rowptr[warp], end = g_rowptr[warp + 1];
    for (int j0 = beg; j0 < end; j0 += 32) {
        int mysrc = (j0 + lane < end) ? g_srcs[j0 + lane] : 0;
        int cnt = min(32, end - j0);
        int u = 0;
        for (; u + 3 < cnt; u += 4) {
            int s1 = __shfl_sync(0xffffffffu, mysrc, u);
            int s2 = __shfl_sync(0xffffffffu, mysrc, u + 1);
            int s3 = __shfl_sync(0xffffffffu, mysrc, u + 2);
            int s4 = __shfl_sync(0xffffffffu, mysrc, u + 3);
            float v1 = xin[(size_t)s1 * 64 + lane];
            float v2 = xin[(size_t)s2 * 64 + lane];
            float v3 = xin[(size_t)s3 * 64 + lane];
            float v4 = xin[(size_t)s4 * 64 + lane];
            float e1 = warpSum(lk(v1 + xrk) * attk);
            float e2 = warpSum(lk(v2 + xrk) * attk);
            float e3 = warpSum(lk(v3 + xrk) * attk);
            float e4 = warpSum(lk(v4 + xrk) * attk);
            float mn = fmaxf(fmaxf(m, fmaxf(e1, e2)), fmaxf(e3, e4));
            float c = __expf(m - mn);
            float p1 = __expf(e1 - mn), p2 = __expf(e2 - mn);
            float p3 = __expf(e3 - mn), p4 = __expf(e4 - mn);
            ssum = fmaf(ssum, c, (p1 + p2) + (p3 + p4));
            acc = fmaf(acc, c, fmaf(p1, v1, p2 * v2) + fmaf(p3, v3, p4 * v4));
            m = mn;
        }
        for (; u < cnt; ++u) {
            int s1 = __shfl_sync(0xffffffffu, mysrc, u);
            float v1 = xin[(size_t)s1 * 64 + lane];
            float e1 = warpSum(lk(v1 + xrk) * attk);
            float mn = fmaxf(m, e1);
            float c = __expf(m - mn), p = __expf(e1 - mn);
            ssum = fmaf(ssum, c, p);
            acc = fmaf(acc, c, p * v1);
            m = mn;
        }
    }
    float o = acc / (ssum + 1e-16f) + bk;
    o = o > 0.f ? o : expm1f(o);
    g_h1[(size_t)warp * 32 + lane] = o;
}

__device__ __forceinline__ float score128(float4 v, float4 xr, float4 a) {
    return lk(v.x + xr.x) * a.x + lk(v.y + xr.y) * a.y +
           lk(v.z + xr.z) * a.z + lk(v.w + xr.w) * a.w;
}

__global__ void k_gat128(const float* __restrict__ att, const float* __restrict__ bias, int N) {
    int warp = (blockIdx.x * blockDim.x + threadIdx.x) >> 5;
    int lane = threadIdx.x & 31;
    if (warp >= N) return;
    const float4* base = reinterpret_cast<const float4*>(g_c2out);
    float4 attk = reinterpret_cast<const float4*>(att)[lane];
    float4 bk = reinterpret_cast<const float4*>(bias)[lane];
    float4 xr4 = base[(size_t)warp * 64 + 32 + lane];
    float4 xl4 = base[(size_t)warp * 64 + lane];
    float m = warpSum(score128(xl4, xr4, attk));
    float ssum = 1.f;
    float4 acc = xl4;
    int beg = g_rowptr[warp], end = g_rowptr[warp + 1];
    for (int j0 = beg; j0 < end; j0 += 32) {
        int mysrc = (j0 + lane < end) ? g_srcs[j0 + lane] : 0;
        int cnt = min(32, end - j0);
        int u = 0;
        for (; u + 3 < cnt; u += 4) {
            int s1 = __shfl_sync(0xffffffffu, mysrc, u);
            int s2 = __shfl_sync(0xffffffffu, mysrc, u + 1);
            int s3 = __shfl_sync(0xffffffffu, mysrc, u + 2);
            int s4 = __shfl_sync(0xffffffffu, mysrc, u + 3);
            float4 v1 = base[(size_t)s1 * 64 + lane];
            float4 v2 = base[(size_t)s2 * 64 + lane];
            float4 v3 = base[(size_t)s3 * 64 + lane];
            float4 v4 = base[(size_t)s4 * 64 + lane];
            float e1 = warpSum(score128(v1, xr4, attk));
            float e2 = warpSum(score128(v2, xr4, attk));
            float e3 = warpSum(score128(v3, xr4, attk));
            float e4 = warpSum(score128(v4, xr4, attk));
            float mn = fmaxf(fmaxf(m, fmaxf(e1, e2)), fmaxf(e3, e4));
            float c = __expf(m - mn);
            float p1 = __expf(e1 - mn), p2 = __expf(e2 - mn);
            float p3 = __expf(e3 - mn), p4 = __expf(e4 - mn);
            ssum = fmaf(ssum, c, (p1 + p2) + (p3 + p4));
            acc.x = fmaf(acc.x, c, fmaf(p1, v1.x, p2 * v2.x) + fmaf(p3, v3.x, p4 * v4.x));
            acc.y = fmaf(acc.y, c, fmaf(p1, v1.y, p2 * v2.y) + fmaf(p3, v3.y, p4 * v4.y));
            acc.z = fmaf(acc.z, c, fmaf(p1, v1.z, p2 * v2.z) + fmaf(p3, v3.z, p4 * v4.z));
            acc.w = fmaf(acc.w, c, fmaf(p1, v1.w, p2 * v2.w) + fmaf(p3, v3.w, p4 * v4.w));
            m = mn;
        }
        for (; u < cnt; ++u) {
            int s1 = __shfl_sync(0xffffffffu, mysrc, u);
            float4 v1 = base[(size_t)s1 * 64 + lane];
            float e1 = warpSum(score128(v1, xr4, attk));
            float mn = fmaxf(m, e1);
            float c = __expf(m - mn), p = __expf(e1 - mn);
            ssum = fmaf(ssum, c, p);
            acc.x = fmaf(acc.x, c, p * v1.x);
            acc.y = fmaf(acc.y, c, p * v1.y);
            acc.z = fmaf(acc.z, c, p * v1.z);
            acc.w = fmaf(acc.w, c, p * v1.w);
            m = mn;
        }
    }
    float inv = 1.f / (ssum + 1e-16f);
    float4 o;
    o.x = acc.x * inv + bk.x; o.y = acc.y * inv + bk.y;
    o.z = acc.z * inv + bk.z; o.w = acc.w * inv + bk.w;
    o.x = o.x > 0.f ? o.x : expm1f(o.x);
    o.y = o.y > 0.f ? o.y : expm1f(o.y);
    o.z = o.z > 0.f ? o.z : expm1f(o.z);
    o.w = o.w > 0.f ? o.w : expm1f(o.w);
    reinterpret_cast<float4*>(g_h2)[(size_t)warp * 32 + lane] = o;
}

// mu/logstd layers: one warp per (node, head). head 0 = mu, head 1 = logstd.
__global__ void k_gat_mh(const float* __restrict__ attm, const float* __restrict__ bm,
                         const float* __restrict__ attl, const float* __restrict__ bl,
                         float* __restrict__ outmu, float* __restrict__ outls, int N) {
    int gw = (blockIdx.x * blockDim.x + threadIdx.x) >> 5;
    int lane = threadIdx.x & 31;
    int node = gw >> 1, head = gw & 1;
    if (node >= N) return;
    const float* att = head ? attl : attm;
    const float* bia = head ? bl : bm;
    float* outp = head ? outls : outmu;
    int off = head * 64;
    float attk = att[lane];
    float bk = bia[lane];
    const float* xin = g_c3out;
    float xrk = xin[(size_t)node * 128 + off + 32 + lane];
    float xlk0 = xin[(size_t)node * 128 + off + lane];
    float m = warpSum(lk(xlk0 + xrk) * attk);
    float ssum = 1.f, acc = xlk0;
    int beg = g_rowptr[node], end = g_rowptr[node + 1];
    for (int j0 = beg; j0 < end; j0 += 32) {
        int mysrc = (j0 + lane < end) ? g_srcs[j0 + lane] : 0;
        int cnt = min(32, end - j0);
        int u = 0;
        for (; u + 3 < cnt; u += 4) {
            int s1 = __shfl_sync(0xffffffffu, mysrc, u);
            int s2 = __shfl_sync(0xffffffffu, mysrc, u + 1);
            int s3 = __shfl_sync(0xffffffffu, mysrc, u + 2);
            int s4 = __shfl_sync(0xffffffffu, mysrc, u + 3);
            float v1 = xin[(size_t)s1 * 128 + off + lane];
            float v2 = xin[(size_t)s2 * 128 + off + lane];
            float v3 = xin[(size_t)s3 * 128 + off + lane];
            float v4 = xin[(size_t)s4 * 128 + off + lane];
            float e1 = warpSum(lk(v1 + xrk) * attk);
            float e2 = warpSum(lk(v2 + xrk) * attk);
            float e3 = warpSum(lk(v3 + xrk) * attk);
            float e4 = warpSum(lk(v4 + xrk) * attk);
            float mn = fmaxf(fmaxf(m, fmaxf(e1, e2)), fmaxf(e3, e4));
            float c = __expf(m - mn);
            float p1 = __expf(e1 - mn), p2 = __expf(e2 - mn);
            float p3 = __expf(e3 - mn), p4 = __expf(e4 - mn);
            ssum = fmaf(ssum, c, (p1 + p2) + (p3 + p4));
            acc = fmaf(acc, c, fmaf(p1, v1, p2 * v2) + fmaf(p3, v3, p4 * v4));
            m = mn;
        }
        for (; u < cnt; ++u) {
            int s1 = __shfl_sync(0xffffffffu, mysrc, u);
            float v1 = xin[(size_t)s1 * 128 + off + lane];
            float e1 = warpSum(lk(v1 + xrk) * attk);
            float mn = fmaxf(m, e1);
            float c = __expf(m - mn), p = __expf(e1 - mn);
            ssum = fmaf(ssum, c, p);
            acc = fmaf(acc, c, p * v1);
            m = mn;
        }
    }
    outp[(size_t)node * 32 + lane] = acc / (ssum + 1e-16f) + bk;
}

// ---------------- threefry + normal + z ----------------
__device__ __forceinline__ uint32_t rotl32(uint32_t v, int r) {
    return (v << r) | (v >> (32 - r));
}

__device__ __forceinline__ void threefry2x32(uint32_t k0, uint32_t k1,
                                             uint32_t& x0, uint32_t& x1) {
    uint32_t ks0 = k0, ks1 = k1, ks2 = k0 ^ k1 ^ 0x1BD11BDAu;
    x0 += ks0; x1 += ks1;
#define RND(r) { x0 += x1; x1 = rotl32(x1, r); x1 ^= x0; }
    RND(13) RND(15) RND(26) RND(6)   x0 += ks1; x1 += ks2 + 1u;
    RND(17) RND(29) RND(16) RND(24)  x0 += ks2; x1 += ks0 + 2u;
    RND(13) RND(15) RND(26) RND(6)   x0 += ks0; x1 += ks1 + 3u;
    RND(17) RND(29) RND(16) RND(24)  x0 += ks1; x1 += ks2 + 4u;
    RND(13) RND(15) RND(26) RND(6)   x0 += ks2; x1 += ks0 + 5u;
#undef RND
}

__device__ __forceinline__ float bits_to_normal(uint32_t bits) {
    float f = __uint_as_float((bits >> 9) | 0x3f800000u) - 1.0f;  // [0,1)
    const float lo = -0.99999994f;
    const float range = 2.0f;
    float u = fmaf(f, range, lo);
    u = fmaxf(u, lo);
    return 1.41421356f * erfinvf(u);
}

// JAX threefry_partitionable: (o0,o1)=threefry2x32(key, 0, i); draw = o0 ^ o1.
__global__ void k_z(float* __restrict__ out, int N) {
    int t = blockIdx.x * blockDim.x + threadIdx.x;
    int T = N * 32;
    if (t >= T) return;
    uint32_t x0 = 0u, x1 = (uint32_t)t;
    threefry2x32(0u, 1u, x0, x1);
    float n = bits_to_normal(x0 ^ x1);
    const float* mu = out;
    const float* ls = out + (size_t)N * 32;
    float* z = out + (size_t)2 * N * 32;
    z[t] = fmaf(n, expf(ls[t]), mu[t]);
}

// ---------------- launch ----------------
extern "C" void kernel_launch(void* const* d_in, const int* in_sizes, int n_in,
                              void* d_out, int out_size) {
    const float* x = (const float*)d_in[0];
    const void* ei = d_in[1];
    const float* Wl_c1 = (const float*)d_in[2];
    const float* Wr_c1 = (const float*)d_in[3];
    const float* att_c1 = (const float*)d_in[4];
    const float* b_c1 = (const float*)d_in[5];
    const float* Wl_c2 = (const float*)d_in[6];
    const float* Wr_c2 = (const float*)d_in[7];
    const float* att_c2 = (const float*)d_in[8];
    const float* b_c2 = (const float*)d_in[9];
    const float* Wl_mu = (const float*)d_in[10];
    const float* Wr_mu = (const float*)d_in[11];
    const float* att_mu = (const float*)d_in[12];
    const float* b_mu = (const float*)d_in[13];
    const float* Wl_ls = (const float*)d_in[14];
    const float* Wr_ls = (const float*)d_in[15];
    const float* att_ls = (const float*)d_in[16];
    const float* b_ls = (const float*)d_in[17];

    const int N = in_sizes[0] / 512;
    const int E = in_sizes[1] / 2;
    float* out = (float*)d_out;

    // ---- prologue ordered so the ncu capture slot (4th launch) hits k_sgemm<0> ----
    k_pack2<<<(512 * 32 + 255) / 256, 256>>>(Wl_c1, Wr_c1, 512, 32);   // 1
    k_zero2<<<(N + 255) / 256, 256>>>(N);                               // 2
    k_probe<<<1, 32>>>((const unsigned int*)ei);                        // 3
    {
        dim3 g((N + 127) / 128, 1);
        k_sgemm<0><<<g, 256>>>(x, N, 64, 512);                          // 4 <-- profiled
    }

    // ---- CSR build (by dst) ----
    k_hist<<<(E + 255) / 256, 256>>>(ei, E, N);
    int nb = (N + 1023) / 1024;
    k_scan1<<<nb, 1024>>>(N);
    k_scan2<<<1, 32>>>(nb);
    k_scan3<<<(N + 255) / 256, 256>>>(N, E);
    k_scatter<<<(E + 255) / 256, 256>>>(ei, E, N);

    // ---- layer c1 edge pass ----
    k_gat32<<<(N * 32 + 255) / 256, 256>>>(att_c1, b_c1, N);

    // ---- layer c2: 32 -> 128 ----
    k_pack2<<<(32 * 128 + 255) / 256, 256>>>(Wl_c2, Wr_c2, 32, 128);
    {
        dim3 g((N + 127) / 128, 4);
        k_sgemm<1><<<g, 256>>>(nullptr, N, 256, 32);
    }
    k_gat128<<<(N * 32 + 255) / 256, 256>>>(att_c2, b_c2, N);

    // ---- layers mu / logstd: 128 -> 32, one warp per (node, head) ----
    k_pack4<<<(128 * 32 + 255) / 256, 256>>>(Wl_mu, Wr_mu, Wl_ls, Wr_ls, 128);
    {
        dim3 g((N + 127) / 128, 2);
        k_sgemm<2><<<g, 256>>>(nullptr, N, 128, 128);
    }
    k_gat_mh<<<(N * 64 + 255) / 256, 256>>>(att_mu, b_mu, att_ls, b_ls,
                                            out, out + (size_t)N * 32, N);

    // ---- reparameterize: z = eps * exp(logstd) + mu ----
    k_z<<<(N * 32 + 255) / 256, 256>>>(out, N);
}

// round 13
// speedup vs baseline: 1.1905x; 1.1905x over previous
#include <cuda_runtime.h>
#include <stdint.h>

// ---------------- static scratch (no runtime alloc allowed) ----------------
#define MAXN 100000
#define MAXE 3200000

__device__ __align__(16) float g_c1out[MAXN * 64];          // [N, 64]  xl_c1 | xr_c1
__device__ __align__(16) float g_h1[MAXN * 32];             // [N, 32]
__device__ __align__(16) float g_c2out[(size_t)MAXN * 256]; // [N,256] xl_c2 | xr_c2
__device__ __align__(16) float g_h2[MAXN * 128];            // [N,128]
__device__ __align__(16) float g_c3out[MAXN * 128];         // [N,128] mu_l|mu_r|ls_l|ls_r
__device__ __align__(16) float g_Wpack[512 * 64];           // packed weights (reused)
__device__ int g_counts[MAXN];
__device__ int g_fill[MAXN];
__device__ int g_rowptr[MAXN + 1];
__device__ int g_srcs[MAXE];
__device__ int g_blockSums[256];
__device__ int g_isI64;

// ---------------- helpers ----------------
__device__ __forceinline__ float warpSum(float v) {
#pragma unroll
    for (int o = 16; o > 0; o >>= 1) v += __shfl_xor_sync(0xffffffffu, v, o);
    return v;
}

__device__ __forceinline__ float lk(float v) { return v > 0.f ? v : 0.2f * v; }

// packed fp32x2 FMA (sm_103a FFMA2) — IEEE fp32 per lane
__device__ __forceinline__ unsigned long long ffma2(unsigned long long a,
                                                    unsigned long long b,
                                                    unsigned long long c) {
    unsigned long long d;
    asm("fma.rn.f32x2 %0, %1, %2, %3;" : "=l"(d) : "l"(a), "l"(b), "l"(c));
    return d;
}
__device__ __forceinline__ unsigned long long pack2(float lo, float hi) {
    unsigned long long r;
    asm("mov.b64 %0, {%1, %2};" : "=l"(r) : "f"(lo), "f"(hi));
    return r;
}
__device__ __forceinline__ void unpack2(unsigned long long v, float& lo, float& hi) {
    asm("mov.b64 {%0, %1}, %2;" : "=f"(lo), "=f"(hi) : "l"(v));
}

// dtype-aware edge-index accessor (int32 vs int64 decided at runtime on device)
__device__ __forceinline__ int edgeIdx(const void* p, long long i) {
    if (g_isI64) return (int)((const long long*)p)[i];
    return ((const int*)p)[i];
}

// ---------------- dtype probe ----------------
__global__ void k_probe(const unsigned int* __restrict__ w) {
    if (threadIdx.x == 0 && blockIdx.x == 0) {
        int allz = 1;
        for (int i = 0; i < 32; i++) allz &= (w[2 * i + 1] == 0u);
        g_isI64 = allz;
    }
}

// ---------------- CSR build ----------------
__global__ void k_zero2(int n) {
    int i = blockIdx.x * blockDim.x + threadIdx.x;
    if (i < n) { g_counts[i] = 0; g_fill[i] = 0; }
}

__global__ void k_hist(const void* __restrict__ ei, int E, int N) {
    int e = blockIdx.x * blockDim.x + threadIdx.x;
    if (e < E) {
        int d = edgeIdx(ei, (long long)E + e);
        if ((unsigned)d < (unsigned)N) atomicAdd(&g_counts[d], 1);
    }
}

__global__ void k_scan1(int n) {  // block=1024
    __shared__ int sm[1024];
    int tid = threadIdx.x;
    int i = blockIdx.x * 1024 + tid;
    int v = (i < n) ? g_counts[i] : 0;
    sm[tid] = v;
    __syncthreads();
#pragma unroll
    for (int off = 1; off < 1024; off <<= 1) {
        int add = (tid >= off) ? sm[tid - off] : 0;
        __syncthreads();
        sm[tid] += add;
        __syncthreads();
    }
    if (i < n) g_rowptr[i] = sm[tid] - v;
    if (tid == 1023) g_blockSums[blockIdx.x] = sm[1023];
}

__global__ void k_scan2(int nb) {
    if (threadIdx.x == 0 && blockIdx.x == 0) {
        int run = 0;
        for (int b = 0; b < nb; b++) { int t = g_blockSums[b]; g_blockSums[b] = run; run += t; }
    }
}

__global__ void k_scan3(int n, int E) {
    int i = blockIdx.x * blockDim.x + threadIdx.x;
    if (i < n) g_rowptr[i] += g_blockSums[i >> 10];
    if (i == 0) g_rowptr[n] = E;
}

__global__ void k_scatter(const void* __restrict__ ei, int E, int N) {
    int e = blockIdx.x * blockDim.x + threadIdx.x;
    if (e < E) {
        int d = edgeIdx(ei, (long long)E + e);
        int s = edgeIdx(ei, e);
        if ((unsigned)d < (unsigned)N && (unsigned)s < (unsigned)N) {
            int p = g_rowptr[d] + atomicAdd(&g_fill[d], 1);
            g_srcs[p] = s;
        }
    }
}

// ---------------- weight packing ----------------
__global__ void k_pack2(const float* __restrict__ Wl, const float* __restrict__ Wr,
                        int K, int D) {
    int i = blockIdx.x * blockDim.x + threadIdx.x;
    if (i >= K * D) return;
    int k = i / D, d = i % D;
    g_Wpack[k * 2 * D + d]     = Wl[i];
    g_Wpack[k * 2 * D + D + d] = Wr[i];
}

__global__ void k_pack4(const float* __restrict__ W0, const float* __restrict__ W1,
                        const float* __restrict__ W2, const float* __restrict__ W3,
                        int K) {
    int i = blockIdx.x * blockDim.x + threadIdx.x;
    if (i >= K * 32) return;
    int k = i / 32, d = i % 32;
    g_Wpack[k * 128 + d]       = W0[i];
    g_Wpack[k * 128 + 32 + d]  = W1[i];
    g_Wpack[k * 128 + 64 + d]  = W2[i];
    g_Wpack[k * 128 + 96 + d]  = W3[i];
}

// ---------------- SGEMM (R11 tile + double-buffered smem pipeline) ----------------
// BM=128 BN=64 BK=16, 256 threads, thread tile 8 rows x 4 cols (4x4 f32x2 accs).
// Two-stage: prefetch tile k+1 into regs during compute of tile k; ONE barrier/iter.
template <int LAYER>
__global__ __launch_bounds__(256, 3) void k_sgemm(const float* __restrict__ Aext,
                                                  int M, int Nn, int K) {
    const float* __restrict__ A = (LAYER == 0) ? Aext : (LAYER == 1 ? g_h1 : g_h2);
    float* __restrict__ C = (LAYER == 0) ? g_c1out : (LAYER == 1 ? g_c2out : g_c3out);
    const float* __restrict__ B = g_Wpack;

    __shared__ float As[2][16][128];
    __shared__ float Bs[2][16][64];
    const int rowBase = blockIdx.x * 128;
    const int colBase = blockIdx.y * 64;
    const int t = threadIdx.x;
    const int tx = t & 15;   // col group (4 cols)
    const int ty = t >> 4;   // row group (8 rows)

    // loader lane mapping (fixed per thread)
    const int rA0 = (t) >> 2, cA0 = (t) & 3;
    const int rA1 = (t + 256) >> 2, cA1 = (t + 256) & 3;
    const int kkB = t >> 4, cB = t & 15;

    unsigned long long acc2[4][4];
#pragma unroll
    for (int i = 0; i < 4; i++)
#pragma unroll
        for (int j = 0; j < 4; j++) acc2[i][j] = 0ull;

    // prologue: load tile 0
    float4 aV0 = make_float4(0.f, 0.f, 0.f, 0.f), aV1 = aV0, bV;
    {
        int g0 = rowBase + rA0, g1 = rowBase + rA1;
        if (g0 < M) aV0 = *reinterpret_cast<const float4*>(A + (size_t)g0 * K + cA0 * 4);
        if (g1 < M) aV1 = *reinterpret_cast<const float4*>(A + (size_t)g1 * K + cA1 * 4);
        bV = *reinterpret_cast<const float4*>(B + (size_t)kkB * Nn + colBase + cB * 4);
    }
    // store stage 0
    As[0][cA0 * 4 + 0][rA0] = aV0.x; As[0][cA0 * 4 + 1][rA0] = aV0.y;
    As[0][cA0 * 4 + 2][rA0] = aV0.z; As[0][cA0 * 4 + 3][rA0] = aV0.w;
    As[0][cA1 * 4 + 0][rA1] = aV1.x; As[0][cA1 * 4 + 1][rA1] = aV1.y;
    As[0][cA1 * 4 + 2][rA1] = aV1.z; As[0][cA1 * 4 + 3][rA1] = aV1.w;
    *reinterpret_cast<float4*>(&Bs[0][kkB][cB * 4]) = bV;
    __syncthreads();

    const int nIter = K >> 4;
    int cur = 0;
    for (int it = 0; it < nIter; ++it) {
        // prefetch next tile into regs (overlaps with compute below)
        float4 aN0, aN1, bN;
        bool havNext = (it + 1 < nIter);
        if (havNext) {
            int k0n = (it + 1) << 4;
            int g0 = rowBase + rA0, g1 = rowBase + rA1;
            aN0 = make_float4(0.f, 0.f, 0.f, 0.f); aN1 = aN0;
            if (g0 < M) aN0 = *reinterpret_cast<const float4*>(A + (size_t)g0 * K + k0n + cA0 * 4);
            if (g1 < M) aN1 = *reinterpret_cast<const float4*>(A + (size_t)g1 * K + k0n + cA1 * 4);
            bN = *reinterpret_cast<const float4*>(B + (size_t)(k0n + kkB) * Nn + colBase + cB * 4);
        }
        // compute on current buffer
#pragma unroll
        for (int k = 0; k < 16; k++) {
            unsigned long long a2[4];
#pragma unroll
            for (int i = 0; i < 4; i++)
                a2[i] = *reinterpret_cast<const unsigned long long*>(&As[cur][k][ty * 8 + i * 2]);
            unsigned long long bd[4];
#pragma unroll
            for (int j = 0; j < 4; j++) {
                float bj = Bs[cur][k][tx * 4 + j];
                bd[j] = pack2(bj, bj);
            }
#pragma unroll
            for (int i = 0; i < 4; i++)
#pragma unroll
                for (int j = 0; j < 4; j++) acc2[i][j] = ffma2(a2[i], bd[j], acc2[i][j]);
        }
        // store prefetched tile to the other buffer
        if (havNext) {
            int nxt = cur ^ 1;
            As[nxt][cA0 * 4 + 0][rA0] = aN0.x; As[nxt][cA0 * 4 + 1][rA0] = aN0.y;
            As[nxt][cA0 * 4 + 2][rA0] = aN0.z; As[nxt][cA0 * 4 + 3][rA0] = aN0.w;
            As[nxt][cA1 * 4 + 0][rA1] = aN1.x; As[nxt][cA1 * 4 + 1][rA1] = aN1.y;
            As[nxt][cA1 * 4 + 2][rA1] = aN1.z; As[nxt][cA1 * 4 + 3][rA1] = aN1.w;
            *reinterpret_cast<float4*>(&Bs[nxt][kkB][cB * 4]) = bN;
            __syncthreads();
        }
        cur ^= 1;
    }
#pragma unroll
    for (int i = 0; i < 4; i++) {
        float lo[4], hi[4];
#pragma unroll
        for (int j = 0; j < 4; j++) unpack2(acc2[i][j], lo[j], hi[j]);
        int r0 = rowBase + ty * 8 + i * 2;
        if (r0 < M)
            *reinterpret_cast<float4*>(C + (size_t)r0 * Nn + colBase + tx * 4) =
                make_float4(lo[0], lo[1], lo[2], lo[3]);
        if (r0 + 1 < M)
            *reinterpret_cast<float4*>(C + (size_t)(r0 + 1) * Nn + colBase + tx * 4) =
                make_float4(hi[0], hi[1], hi[2], hi[3]);
    }
}

// ---------------- GATv2 edge kernels (4-edge unroll online softmax — R11) ----------------
__global__ void k_gat32(const float* __restrict__ att, const float* __restrict__ bias, int N) {
    int warp = (blockIdx.x * blockDim.x + threadIdx.x) >> 5;
    int lane = threadIdx.x & 31;
    if (warp >= N) return;
    float attk = att[lane];
    float bk = bias[lane];
    const float* xin = g_c1out;
    float xrk = xin[(size_t)warp * 64 + 32 + lane];
    float xlk0 = xin[(size_t)warp * 64 + lane];
    float m = warpSum(lk(xlk0 + xrk) * attk);
    float ssum = 1.f, acc = xlk0;
    int beg = g_rowptr[warp], end = g_rowptr[warp + 1];
    for (int j0 = beg; j0 < end; j0 += 32) {
        int mysrc = (j0 + lane < end) ? g_srcs[j0 + lane] : 0;
        int cnt = min(32, end - j0);
        int u = 0;
        for (; u + 3 < cnt; u += 4) {
            int s1 = __shfl_sync(0xffffffffu, mysrc, u);
            int s2 = __shfl_sync(0xffffffffu, mysrc, u + 1);
            int s3 = __shfl_sync(0xffffffffu, mysrc, u + 2);
            int s4 = __shfl_sync(0xffffffffu, mysrc, u + 3);
            float v1 = xin[(size_t)s1 * 64 + lane];
            float v2 = xin[(size_t)s2 * 64 + lane];
            float v3 = xin[(size_t)s3 * 64 + lane];
            float v4 = xin[(size_t)s4 * 64 + lane];
            float e1 = warpSum(lk(v1 + xrk) * attk);
            float e2 = warpSum(lk(v2 + xrk) * attk);
            float e3 = warpSum(lk(v3 + xrk) * attk);
            float e4 = warpSum(lk(v4 + xrk) * attk);
            float mn = fmaxf(fmaxf(m, fmaxf(e1, e2)), fmaxf(e3, e4));
            float c = __expf(m - mn);
            float p1 = __expf(e1 - mn), p2 = __expf(e2 - mn);
            float p3 = __expf(e3 - mn), p4 = __expf(e4 - mn);
            ssum = fmaf(ssum, c, (p1 + p2) + (p3 + p4));
            acc = fmaf(acc, c, fmaf(p1, v1, p2 * v2) + fmaf(p3, v3, p4 * v4));
            m = mn;
        }
        for (; u < cnt; ++u) {
            int s1 = __shfl_sync(0xffffffffu, mysrc, u);
            float v1 = xin[(size_t)s1 * 64 + lane];
            float e1 = warpSum(lk(v1 + xrk) * attk);
            float mn = fmaxf(m, e1);
            float c = __expf(m - mn), p = __expf(e1 - mn);
            ssum = fmaf(ssum, c, p);
            acc = fmaf(acc, c, p * v1);
            m = mn;
        }
    }
    float o = acc / (ssum + 1e-16f) + bk;
    o = o > 0.f ? o : expm1f(o);
    g_h1[(size_t)warp * 32 + lane] = o;
}

__device__ __forceinline__ float score128(float4 v, float4 xr, float4 a) {
    return lk(v.x + xr.x) * a.x + lk(v.y + xr.y) * a.y +
           lk(v.z + xr.z) * a.z + lk(v.w + xr.w) * a.w;
}

__global__ void k_gat128(const float* __restrict__ att, const float* __restrict__ bias, int N) {
    int warp = (blockIdx.x * blockDim.x + threadIdx.x) >> 5;
    int lane = threadIdx.x & 31;
    if (warp >= N) return;
    const float4* base = reinterpret_cast<const float4*>(g_c2out);
    float4 attk = reinterpret_cast<const float4*>(att)[lane];
    float4 bk = reinterpret_cast<const float4*>(bias)[lane];
    float4 xr4 = base[(size_t)warp * 64 + 32 + lane];
    float4 xl4 = base[(size_t)warp * 64 + lane];
    float m = warpSum(score128(xl4, xr4, attk));
    float ssum = 1.f;
    float4 acc = xl4;
    int beg = g_rowptr[warp], end = g_rowptr[warp + 1];
    for (int j0 = beg; j0 < end; j0 += 32) {
        int mysrc = (j0 + lane < end) ? g_srcs[j0 + lane] : 0;
        int cnt = min(32, end - j0);
        int u = 0;
        for (; u + 3 < cnt; u += 4) {
            int s1 = __shfl_sync(0xffffffffu, mysrc, u);
            int s2 = __shfl_sync(0xffffffffu, mysrc, u + 1);
            int s3 = __shfl_sync(0xffffffffu, mysrc, u + 2);
            int s4 = __shfl_sync(0xffffffffu, mysrc, u + 3);
            float4 v1 = base[(size_t)s1 * 64 + lane];
            float4 v2 = base[(size_t)s2 * 64 + lane];
            float4 v3 = base[(size_t)s3 * 64 + lane];
            float4 v4 = base[(size_t)s4 * 64 + lane];
            float e1 = warpSum(score128(v1, xr4, attk));
            float e2 = warpSum(score128(v2, xr4, attk));
            float e3 = warpSum(score128(v3, xr4, attk));
            float e4 = warpSum(score128(v4, xr4, attk));
            float mn = fmaxf(fmaxf(m, fmaxf(e1, e2)), fmaxf(e3, e4));
            float c = __expf(m - mn);
            float p1 = __expf(e1 - mn), p2 = __expf(e2 - mn);
            float p3 = __expf(e3 - mn), p4 = __expf(e4 - mn);
            ssum = fmaf(ssum, c, (p1 + p2) + (p3 + p4));
            acc.x = fmaf(acc.x, c, fmaf(p1, v1.x, p2 * v2.x) + fmaf(p3, v3.x, p4 * v4.x));
            acc.y = fmaf(acc.y, c, fmaf(p1, v1.y, p2 * v2.y) + fmaf(p3, v3.y, p4 * v4.y));
            acc.z = fmaf(acc.z, c, fmaf(p1, v1.z, p2 * v2.z) + fmaf(p3, v3.z, p4 * v4.z));
            acc.w = fmaf(acc.w, c, fmaf(p1, v1.w, p2 * v2.w) + fmaf(p3, v3.w, p4 * v4.w));
            m = mn;
        }
        for (; u < cnt; ++u) {
            int s1 = __shfl_sync(0xffffffffu, mysrc, u);
            float4 v1 = base[(size_t)s1 * 64 + lane];
            float e1 = warpSum(score128(v1, xr4, attk));
            float mn = fmaxf(m, e1);
            float c = __expf(m - mn), p = __expf(e1 - mn);
            ssum = fmaf(ssum, c, p);
            acc.x = fmaf(acc.x, c, p * v1.x);
            acc.y = fmaf(acc.y, c, p * v1.y);
            acc.z = fmaf(acc.z, c, p * v1.z);
            acc.w = fmaf(acc.w, c, p * v1.w);
            m = mn;
        }
    }
    float inv = 1.f / (ssum + 1e-16f);
    float4 o;
    o.x = acc.x * inv + bk.x; o.y = acc.y * inv + bk.y;
    o.z = acc.z * inv + bk.z; o.w = acc.w * inv + bk.w;
    o.x = o.x > 0.f ? o.x : expm1f(o.x);
    o.y = o.y > 0.f ? o.y : expm1f(o.y);
    o.z = o.z > 0.f ? o.z : expm1f(o.z);
    o.w = o.w > 0.f ? o.w : expm1f(o.w);
    reinterpret_cast<float4*>(g_h2)[(size_t)warp * 32 + lane] = o;
}

// mu/logstd layers: one warp per (node, head). head 0 = mu, head 1 = logstd.
__global__ void k_gat_mh(const float* __restrict__ attm, const float* __restrict__ bm,
                         const float* __restrict__ attl, const float* __restrict__ bl,
                         float* __restrict__ outmu, float* __restrict__ outls, int N) {
    int gw = (blockIdx.x * blockDim.x + threadIdx.x) >> 5;
    int lane = threadIdx.x & 31;
    int node = gw >> 1, head = gw & 1;
    if (node >= N) return;
    const float* att = head ? attl : attm;
    const float* bia = head ? bl : bm;
    float* outp = head ? outls : outmu;
    int off = head * 64;
    float attk = att[lane];
    float bk = bia[lane];
    const float* xin = g_c3out;
    float xrk = xin[(size_t)node * 128 + off + 32 + lane];
    float xlk0 = xin[(size_t)node * 128 + off + lane];
    float m = warpSum(lk(xlk0 + xrk) * attk);
    float ssum = 1.f, acc = xlk0;
    int beg = g_rowptr[node], end = g_rowptr[node + 1];
    for (int j0 = beg; j0 < end; j0 += 32) {
        int mysrc = (j0 + lane < end) ? g_srcs[j0 + lane] : 0;
        int cnt = min(32, end - j0);
        int u = 0;
        for (; u + 3 < cnt; u += 4) {
            int s1 = __shfl_sync(0xffffffffu, mysrc, u);
            int s2 = __shfl_sync(0xffffffffu, mysrc, u + 1);
            int s3 = __shfl_sync(0xffffffffu, mysrc, u + 2);
            int s4 = __shfl_sync(0xffffffffu, mysrc, u + 3);
            float v1 = xin[(size_t)s1 * 128 + off + lane];
            float v2 = xin[(size_t)s2 * 128 + off + lane];
            float v3 = xin[(size_t)s3 * 128 + off + lane];
            float v4 = xin[(size_t)s4 * 128 + off + lane];
            float e1 = warpSum(lk(v1 + xrk) * attk);
            float e2 = warpSum(lk(v2 + xrk) * attk);
            float e3 = warpSum(lk(v3 + xrk) * attk);
            float e4 = warpSum(lk(v4 + xrk) * attk);
            float mn = fmaxf(fmaxf(m, fmaxf(e1, e2)), fmaxf(e3, e4));
            float c = __expf(m - mn);
            float p1 = __expf(e1 - mn), p2 = __expf(e2 - mn);
            float p3 = __expf(e3 - mn), p4 = __expf(e4 - mn);
            ssum = fmaf(ssum, c, (p1 + p2) + (p3 + p4));
            acc = fmaf(acc, c, fmaf(p1, v1, p2 * v2) + fmaf(p3, v3, p4 * v4));
            m = mn;
        }
        for (; u < cnt; ++u) {
            int s1 = __shfl_sync(0xffffffffu, mysrc, u);
            float v1 = xin[(size_t)s1 * 128 + off + lane];
            float e1 = warpSum(lk(v1 + xrk) * attk);
            float mn = fmaxf(m, e1);
            float c = __expf(m - mn), p = __expf(e1 - mn);
            ssum = fmaf(ssum, c, p);
            acc = fmaf(acc, c, p * v1);
            m = mn;
        }
    }
    outp[(size_t)node * 32 + lane] = acc / (ssum + 1e-16f) + bk;
}

// ---------------- threefry + normal + z ----------------
__device__ __forceinline__ uint32_t rotl32(uint32_t v, int r) {
    return (v << r) | (v >> (32 - r));
}

__device__ __forceinline__ void threefry2x32(uint32_t k0, uint32_t k1,
                                             uint32_t& x0, uint32_t& x1) {
    uint32_t ks0 = k0, ks1 = k1, ks2 = k0 ^ k1 ^ 0x1BD11BDAu;
    x0 += ks0; x1 += ks1;
#define RND(r) { x0 += x1; x1 = rotl32(x1, r); x1 ^= x0; }
    RND(13) RND(15) RND(26) RND(6)   x0 += ks1; x1 += ks2 + 1u;
    RND(17) RND(29) RND(16) RND(24)  x0 += ks2; x1 += ks0 + 2u;
    RND(13) RND(15) RND(26) RND(6)   x0 += ks0; x1 += ks1 + 3u;
    RND(17) RND(29) RND(16) RND(24)  x0 += ks1; x1 += ks2 + 4u;
    RND(13) RND(15) RND(26) RND(6)   x0 += ks2; x1 += ks0 + 5u;
#undef RND
}

__device__ __forceinline__ float bits_to_normal(uint32_t bits) {
    float f = __uint_as_float((bits >> 9) | 0x3f800000u) - 1.0f;  // [0,1)
    const float lo = -0.99999994f;
    const float range = 2.0f;
    float u = fmaf(f, range, lo);
    u = fmaxf(u, lo);
    return 1.41421356f * erfinvf(u);
}

// JAX threefry_partitionable: (o0,o1)=threefry2x32(key, 0, i); draw = o0 ^ o1.
__global__ void k_z(float* __restrict__ out, int N) {
    int t = blockIdx.x * blockDim.x + threadIdx.x;
    int T = N * 32;
    if (t >= T) return;
    uint32_t x0 = 0u, x1 = (uint32_t)t;
    threefry2x32(0u, 1u, x0, x1);
    float n = bits_to_normal(x0 ^ x1);
    const float* mu = out;
    const float* ls = out + (size_t)N * 32;
    float* z = out + (size_t)2 * N * 32;
    z[t] = fmaf(n, expf(ls[t]), mu[t]);
}

// ---------------- launch ----------------
extern "C" void kernel_launch(void* const* d_in, const int* in_sizes, int n_in,
                              void* d_out, int out_size) {
    const float* x = (const float*)d_in[0];
    const void* ei = d_in[1];
    const float* Wl_c1 = (const float*)d_in[2];
    const float* Wr_c1 = (const float*)d_in[3];
    const float* att_c1 = (const float*)d_in[4];
    const float* b_c1 = (const float*)d_in[5];
    const float* Wl_c2 = (const float*)d_in[6];
    const float* Wr_c2 = (const float*)d_in[7];
    const float* att_c2 = (const float*)d_in[8];
    const float* b_c2 = (const float*)d_in[9];
    const float* Wl_mu = (const float*)d_in[10];
    const float* Wr_mu = (const float*)d_in[11];
    const float* att_mu = (const float*)d_in[12];
    const float* b_mu = (const float*)d_in[13];
    const float* Wl_ls = (const float*)d_in[14];
    const float* Wr_ls = (const float*)d_in[15];
    const float* att_ls = (const float*)d_in[16];
    const float* b_ls = (const float*)d_in[17];

    const int N = in_sizes[0] / 512;
    const int E = in_sizes[1] / 2;
    float* out = (float*)d_out;

    // ---- prologue ordered so the ncu capture slot (4th launch) hits k_sgemm<0> ----
    k_pack2<<<(512 * 32 + 255) / 256, 256>>>(Wl_c1, Wr_c1, 512, 32);   // 1
    k_zero2<<<(N + 255) / 256, 256>>>(N);                               // 2
    k_probe<<<1, 32>>>((const unsigned int*)ei);                        // 3
    {
        dim3 g((N + 127) / 128, 1);
        k_sgemm<0><<<g, 256>>>(x, N, 64, 512);                          // 4 <-- profiled
    }

    // ---- CSR build (by dst) ----
    k_hist<<<(E + 255) / 256, 256>>>(ei, E, N);
    int nb = (N + 1023) / 1024;
    k_scan1<<<nb, 1024>>>(N);
    k_scan2<<<1, 32>>>(nb);
    k_scan3<<<(N + 255) / 256, 256>>>(N, E);
    k_scatter<<<(E + 255) / 256, 256>>>(ei, E, N);

    // ---- layer c1 edge pass ----
    k_gat32<<<(N * 32 + 255) / 256, 256>>>(att_c1, b_c1, N);

    // ---- layer c2: 32 -> 128 ----
    k_pack2<<<(32 * 128 + 255) / 256, 256>>>(Wl_c2, Wr_c2, 32, 128);
    {
        dim3 g((N + 127) / 128, 4);
        k_sgemm<1><<<g, 256>>>(nullptr, N, 256, 32);
    }
    k_gat128<<<(N * 32 + 255) / 256, 256>>>(att_c2, b_c2, N);

    // ---- layers mu / logstd: 128 -> 32, one warp per (node, head) ----
    k_pack4<<<(128 * 32 + 255) / 256, 256>>>(Wl_mu, Wr_mu, Wl_ls, Wr_ls, 128);
    {
        dim3 g((N + 127) / 128, 2);
        k_sgemm<2><<<g, 256>>>(nullptr, N, 128, 128);
    }
    k_gat_mh<<<(N * 64 + 255) / 256, 256>>>(att_mu, b_mu, att_ls, b_ls,
                                            out, out + (size_t)N * 32, N);

    // ---- reparameterize: z = eps * exp(logstd) + mu ----
    k_z<<<(N * 32 + 255) / 256, 256>>>(out, N);
}

// round 14
// speedup vs baseline: 1.2058x; 1.0128x over previous
#include <cuda_runtime.h>
#include <cuda_fp16.h>
#include <stdint.h>

// ---------------- static scratch (no runtime alloc allowed) ----------------
#define MAXN 100000
#define MAXE 3200000

__device__ __align__(16) float g_c1out[MAXN * 64];          // [N, 64]  xl_c1 | xr_c1
__device__ __align__(16) float g_h1[MAXN * 32];             // [N, 32]
__device__ __align__(16) __half g_c2h[(size_t)MAXN * 256];  // [N,256] fp16 xl_c2 | xr_c2
__device__ __align__(16) float g_h2[MAXN * 128];            // [N,128]
__device__ __align__(16) float g_c3out[MAXN * 128];         // [N,128] mu_l|mu_r|ls_l|ls_r
__device__ __align__(16) float g_Wpack[512 * 64];           // packed weights (reused)
__device__ int g_counts[MAXN];
__device__ int g_fill[MAXN];
__device__ int g_rowptr[MAXN + 1];
__device__ int g_srcs[MAXE];
__device__ int g_blockSums[256];
__device__ int g_isI64;

// ---------------- helpers ----------------
__device__ __forceinline__ float warpSum(float v) {
#pragma unroll
    for (int o = 16; o > 0; o >>= 1) v += __shfl_xor_sync(0xffffffffu, v, o);
    return v;
}

__device__ __forceinline__ float lk(float v) { return v > 0.f ? v : 0.2f * v; }

// packed fp32x2 FMA (sm_103a FFMA2) — IEEE fp32 per lane
__device__ __forceinline__ unsigned long long ffma2(unsigned long long a,
                                                    unsigned long long b,
                                                    unsigned long long c) {
    unsigned long long d;
    asm("fma.rn.f32x2 %0, %1, %2, %3;" : "=l"(d) : "l"(a), "l"(b), "l"(c));
    return d;
}
__device__ __forceinline__ unsigned long long pack2(float lo, float hi) {
    unsigned long long r;
    asm("mov.b64 %0, {%1, %2};" : "=l"(r) : "f"(lo), "f"(hi));
    return r;
}
__device__ __forceinline__ void unpack2(unsigned long long v, float& lo, float& hi) {
    asm("mov.b64 {%0, %1}, %2;" : "=f"(lo), "=f"(hi) : "l"(v));
}

// load 4 halves (8B) and widen to float4
__device__ __forceinline__ float4 ldh4(const uint2* __restrict__ p, size_t idx) {
    uint2 r = p[idx];
    __half2 a = *reinterpret_cast<__half2*>(&r.x);
    __half2 b = *reinterpret_cast<__half2*>(&r.y);
    float2 fa = __half22float2(a), fb = __half22float2(b);
    return make_float4(fa.x, fa.y, fb.x, fb.y);
}

// dtype-aware edge-index accessor (int32 vs int64 decided at runtime on device)
__device__ __forceinline__ int edgeIdx(const void* p, long long i) {
    if (g_isI64) return (int)((const long long*)p)[i];
    return ((const int*)p)[i];
}

// ---------------- dtype probe ----------------
__global__ void k_probe(const unsigned int* __restrict__ w) {
    if (threadIdx.x == 0 && blockIdx.x == 0) {
        int allz = 1;
        for (int i = 0; i < 32; i++) allz &= (w[2 * i + 1] == 0u);
        g_isI64 = allz;
    }
}

// ---------------- CSR build ----------------
__global__ void k_zero2(int n) {
    int i = blockIdx.x * blockDim.x + threadIdx.x;
    if (i < n) { g_counts[i] = 0; g_fill[i] = 0; }
}

__global__ void k_hist(const void* __restrict__ ei, int E, int N) {
    int e = blockIdx.x * blockDim.x + threadIdx.x;
    if (e < E) {
        int d = edgeIdx(ei, (long long)E + e);
        if ((unsigned)d < (unsigned)N) atomicAdd(&g_counts[d], 1);
    }
}

__global__ void k_scan1(int n) {  // block=1024
    __shared__ int sm[1024];
    int tid = threadIdx.x;
    int i = blockIdx.x * 1024 + tid;
    int v = (i < n) ? g_counts[i] : 0;
    sm[tid] = v;
    __syncthreads();
#pragma unroll
    for (int off = 1; off < 1024; off <<= 1) {
        int add = (tid >= off) ? sm[tid - off] : 0;
        __syncthreads();
        sm[tid] += add;
        __syncthreads();
    }
    if (i < n) g_rowptr[i] = sm[tid] - v;
    if (tid == 1023) g_blockSums[blockIdx.x] = sm[1023];
}

__global__ void k_scan2(int nb) {
    if (threadIdx.x == 0 && blockIdx.x == 0) {
        int run = 0;
        for (int b = 0; b < nb; b++) { int t = g_blockSums[b]; g_blockSums[b] = run; run += t; }
    }
}

__global__ void k_scan3(int n, int E) {
    int i = blockIdx.x * blockDim.x + threadIdx.x;
    if (i < n) g_rowptr[i] += g_blockSums[i >> 10];
    if (i == 0) g_rowptr[n] = E;
}

__global__ void k_scatter(const void* __restrict__ ei, int E, int N) {
    int e = blockIdx.x * blockDim.x + threadIdx.x;
    if (e < E) {
        int d = edgeIdx(ei, (long long)E + e);
        int s = edgeIdx(ei, e);
        if ((unsigned)d < (unsigned)N && (unsigned)s < (unsigned)N) {
            int p = g_rowptr[d] + atomicAdd(&g_fill[d], 1);
            g_srcs[p] = s;
        }
    }
}

// ---------------- weight packing ----------------
__global__ void k_pack2(const float* __restrict__ Wl, const float* __restrict__ Wr,
                        int K, int D) {
    int i = blockIdx.x * blockDim.x + threadIdx.x;
    if (i >= K * D) return;
    int k = i / D, d = i % D;
    g_Wpack[k * 2 * D + d]     = Wl[i];
    g_Wpack[k * 2 * D + D + d] = Wr[i];
}

__global__ void k_pack4(const float* __restrict__ W0, const float* __restrict__ W1,
                        const float* __restrict__ W2, const float* __restrict__ W3,
                        int K) {
    int i = blockIdx.x * blockDim.x + threadIdx.x;
    if (i >= K * 32) return;
    int k = i / 32, d = i % 32;
    g_Wpack[k * 128 + d]       = W0[i];
    g_Wpack[k * 128 + 32 + d]  = W1[i];
    g_Wpack[k * 128 + 64 + d]  = W2[i];
    g_Wpack[k * 128 + 96 + d]  = W3[i];
}

// ---------------- SGEMM (R13: double-buffered, 8x4 tile, FFMA2) ----------------
// LAYER 1 stores its output as fp16 into g_c2h (halves write traffic, L2-resident gather table).
template <int LAYER>
__global__ __launch_bounds__(256, 3) void k_sgemm(const float* __restrict__ Aext,
                                                  int M, int Nn, int K) {
    const float* __restrict__ A = (LAYER == 0) ? Aext : (LAYER == 1 ? g_h1 : g_h2);
    float* __restrict__ C = (LAYER == 0) ? g_c1out : (LAYER == 1 ? nullptr : g_c3out);
    const float* __restrict__ B = g_Wpack;

    __shared__ float As[2][16][128];
    __shared__ float Bs[2][16][64];
    const int rowBase = blockIdx.x * 128;
    const int colBase = blockIdx.y * 64;
    const int t = threadIdx.x;
    const int tx = t & 15;   // col group (4 cols)
    const int ty = t >> 4;   // row group (8 rows)

    const int rA0 = (t) >> 2, cA0 = (t) & 3;
    const int rA1 = (t + 256) >> 2, cA1 = (t + 256) & 3;
    const int kkB = t >> 4, cB = t & 15;

    unsigned long long acc2[4][4];
#pragma unroll
    for (int i = 0; i < 4; i++)
#pragma unroll
        for (int j = 0; j < 4; j++) acc2[i][j] = 0ull;

    float4 aV0 = make_float4(0.f, 0.f, 0.f, 0.f), aV1 = aV0, bV;
    {
        int g0 = rowBase + rA0, g1 = rowBase + rA1;
        if (g0 < M) aV0 = *reinterpret_cast<const float4*>(A + (size_t)g0 * K + cA0 * 4);
        if (g1 < M) aV1 = *reinterpret_cast<const float4*>(A + (size_t)g1 * K + cA1 * 4);
        bV = *reinterpret_cast<const float4*>(B + (size_t)kkB * Nn + colBase + cB * 4);
    }
    As[0][cA0 * 4 + 0][rA0] = aV0.x; As[0][cA0 * 4 + 1][rA0] = aV0.y;
    As[0][cA0 * 4 + 2][rA0] = aV0.z; As[0][cA0 * 4 + 3][rA0] = aV0.w;
    As[0][cA1 * 4 + 0][rA1] = aV1.x; As[0][cA1 * 4 + 1][rA1] = aV1.y;
    As[0][cA1 * 4 + 2][rA1] = aV1.z; As[0][cA1 * 4 + 3][rA1] = aV1.w;
    *reinterpret_cast<float4*>(&Bs[0][kkB][cB * 4]) = bV;
    __syncthreads();

    const int nIter = K >> 4;
    int cur = 0;
    for (int it = 0; it < nIter; ++it) {
        float4 aN0, aN1, bN;
        bool havNext = (it + 1 < nIter);
        if (havNext) {
            int k0n = (it + 1) << 4;
            int g0 = rowBase + rA0, g1 = rowBase + rA1;
            aN0 = make_float4(0.f, 0.f, 0.f, 0.f); aN1 = aN0;
            if (g0 < M) aN0 = *reinterpret_cast<const float4*>(A + (size_t)g0 * K + k0n + cA0 * 4);
            if (g1 < M) aN1 = *reinterpret_cast<const float4*>(A + (size_t)g1 * K + k0n + cA1 * 4);
            bN = *reinterpret_cast<const float4*>(B + (size_t)(k0n + kkB) * Nn + colBase + cB * 4);
        }
#pragma unroll
        for (int k = 0; k < 16; k++) {
            unsigned long long a2[4];
#pragma unroll
            for (int i = 0; i < 4; i++)
                a2[i] = *reinterpret_cast<const unsigned long long*>(&As[cur][k][ty * 8 + i * 2]);
            unsigned long long bd[4];
#pragma unroll
            for (int j = 0; j < 4; j++) {
                float bj = Bs[cur][k][tx * 4 + j];
                bd[j] = pack2(bj, bj);
            }
#pragma unroll
            for (int i = 0; i < 4; i++)
#pragma unroll
                for (int j = 0; j < 4; j++) acc2[i][j] = ffma2(a2[i], bd[j], acc2[i][j]);
        }
        if (havNext) {
            int nxt = cur ^ 1;
            As[nxt][cA0 * 4 + 0][rA0] = aN0.x; As[nxt][cA0 * 4 + 1][rA0] = aN0.y;
            As[nxt][cA0 * 4 + 2][rA0] = aN0.z; As[nxt][cA0 * 4 + 3][rA0] = aN0.w;
            As[nxt][cA1 * 4 + 0][rA1] = aN1.x; As[nxt][cA1 * 4 + 1][rA1] = aN1.y;
            As[nxt][cA1 * 4 + 2][rA1] = aN1.z; As[nxt][cA1 * 4 + 3][rA1] = aN1.w;
            *reinterpret_cast<float4*>(&Bs[nxt][kkB][cB * 4]) = bN;
            __syncthreads();
        }
        cur ^= 1;
    }
#pragma unroll
    for (int i = 0; i < 4; i++) {
        float lo[4], hi[4];
#pragma unroll
        for (int j = 0; j < 4; j++) unpack2(acc2[i][j], lo[j], hi[j]);
        int r0 = rowBase + ty * 8 + i * 2;
        if (LAYER == 1) {
            // store fp16 into g_c2h
            if (r0 < M) {
                __half2 h01 = __floats2half2_rn(lo[0], lo[1]);
                __half2 h23 = __floats2half2_rn(lo[2], lo[3]);
                uint2 r; r.x = *reinterpret_cast<unsigned*>(&h01); r.y = *reinterpret_cast<unsigned*>(&h23);
                *reinterpret_cast<uint2*>(&g_c2h[(size_t)r0 * Nn + colBase + tx * 4]) = r;
            }
            if (r0 + 1 < M) {
                __half2 h01 = __floats2half2_rn(hi[0], hi[1]);
                __half2 h23 = __floats2half2_rn(hi[2], hi[3]);
                uint2 r; r.x = *reinterpret_cast<unsigned*>(&h01); r.y = *reinterpret_cast<unsigned*>(&h23);
                *reinterpret_cast<uint2*>(&g_c2h[(size_t)(r0 + 1) * Nn + colBase + tx * 4]) = r;
            }
        } else {
            if (r0 < M)
                *reinterpret_cast<float4*>(C + (size_t)r0 * Nn + colBase + tx * 4) =
                    make_float4(lo[0], lo[1], lo[2], lo[3]);
            if (r0 + 1 < M)
                *reinterpret_cast<float4*>(C + (size_t)(r0 + 1) * Nn + colBase + tx * 4) =
                    make_float4(hi[0], hi[1], hi[2], hi[3]);
        }
    }
}

// ---------------- GATv2 edge kernels (4-edge unroll online softmax) ----------------
__global__ void k_gat32(const float* __restrict__ att, const float* __restrict__ bias, int N) {
    int warp = (blockIdx.x * blockDim.x + threadIdx.x) >> 5;
    int lane = threadIdx.x & 31;
    if (warp >= N) return;
    float attk = att[lane];
    float bk = bias[lane];
    const float* xin = g_c1out;
    float xrk = xin[(size_t)warp * 64 + 32 + lane];
    float xlk0 = xin[(size_t)warp * 64 + lane];
    float m = warpSum(lk(xlk0 + xrk) * attk);
    float ssum = 1.f, acc = xlk0;
    int beg = g_rowptr[warp], end = g_rowptr[warp + 1];
    for (int j0 = beg; j0 < end; j0 += 32) {
        int mysrc = (j0 + lane < end) ? g_srcs[j0 + lane] : 0;
        int cnt = min(32, end - j0);
        int u = 0;
        for (; u + 3 < cnt; u += 4) {
            int s1 = __shfl_sync(0xffffffffu, mysrc, u);
            int s2 = __shfl_sync(0xffffffffu, mysrc, u + 1);
            int s3 = __shfl_sync(0xffffffffu, mysrc, u + 2);
            int s4 = __shfl_sync(0xffffffffu, mysrc, u + 3);
            float v1 = xin[(size_t)s1 * 64 + lane];
            float v2 = xin[(size_t)s2 * 64 + lane];
            float v3 = xin[(size_t)s3 * 64 + lane];
            float v4 = xin[(size_t)s4 * 64 + lane];
            float e1 = warpSum(lk(v1 + xrk) * attk);
            float e2 = warpSum(lk(v2 + xrk) * attk);
            float e3 = warpSum(lk(v3 + xrk) * attk);
            float e4 = warpSum(lk(v4 + xrk) * attk);
            float mn = fmaxf(fmaxf(m, fmaxf(e1, e2)), fmaxf(e3, e4));
            float c = __expf(m - mn);
            float p1 = __expf(e1 - mn), p2 = __expf(e2 - mn);
            float p3 = __expf(e3 - mn), p4 = __expf(e4 - mn);
            ssum = fmaf(ssum, c, (p1 + p2) + (p3 + p4));
            acc = fmaf(acc, c, fmaf(p1, v1, p2 * v2) + fmaf(p3, v3, p4 * v4));
            m = mn;
        }
        for (; u < cnt; ++u) {
            int s1 = __shfl_sync(0xffffffffu, mysrc, u);
            float v1 = xin[(size_t)s1 * 64 + lane];
            float e1 = warpSum(lk(v1 + xrk) * attk);
            float mn = fmaxf(m, e1);
            float c = __expf(m - mn), p = __expf(e1 - mn);
            ssum = fmaf(ssum, c, p);
            acc = fmaf(acc, c, p * v1);
            m = mn;
        }
    }
    float o = acc / (ssum + 1e-16f) + bk;
    o = o > 0.f ? o : expm1f(o);
    g_h1[(size_t)warp * 32 + lane] = o;
}

__device__ __forceinline__ float score128(float4 v, float4 xr, float4 a) {
    return lk(v.x + xr.x) * a.x + lk(v.y + xr.y) * a.y +
           lk(v.z + xr.z) * a.z + lk(v.w + xr.w) * a.w;
}

// layer-2 edge pass: gathers fp16 table g_c2h (8B per lane), math in fp32.
__global__ void k_gat128(const float* __restrict__ att, const float* __restrict__ bias, int N) {
    int warp = (blockIdx.x * blockDim.x + threadIdx.x) >> 5;
    int lane = threadIdx.x & 31;
    if (warp >= N) return;
    const uint2* baseh = reinterpret_cast<const uint2*>(g_c2h);  // 64 uint2 per row
    float4 attk = reinterpret_cast<const float4*>(att)[lane];
    float4 bk = reinterpret_cast<const float4*>(bias)[lane];
    float4 xr4 = ldh4(baseh, (size_t)warp * 64 + 32 + lane);
    float4 xl4 = ldh4(baseh, (size_t)warp * 64 + lane);
    float m = warpSum(score128(xl4, xr4, attk));
    float ssum = 1.f;
    float4 acc = xl4;
    int beg = g_rowptr[warp], end = g_rowptr[warp + 1];
    for (int j0 = beg; j0 < end; j0 += 32) {
        int mysrc = (j0 + lane < end) ? g_srcs[j0 + lane] : 0;
        int cnt = min(32, end - j0);
        int u = 0;
        for (; u + 3 < cnt; u += 4) {
            int s1 = __shfl_sync(0xffffffffu, mysrc, u);
            int s2 = __shfl_sync(0xffffffffu, mysrc, u + 1);
            int s3 = __shfl_sync(0xffffffffu, mysrc, u + 2);
            int s4 = __shfl_sync(0xffffffffu, mysrc, u + 3);
            float4 v1 = ldh4(baseh, (size_t)s1 * 64 + lane);
            float4 v2 = ldh4(baseh, (size_t)s2 * 64 + lane);
            float4 v3 = ldh4(baseh, (size_t)s3 * 64 + lane);
            float4 v4 = ldh4(baseh, (size_t)s4 * 64 + lane);
            float e1 = warpSum(score128(v1, xr4, attk));
            float e2 = warpSum(score128(v2, xr4, attk));
            float e3 = warpSum(score128(v3, xr4, attk));
            float e4 = warpSum(score128(v4, xr4, attk));
            float mn = fmaxf(fmaxf(m, fmaxf(e1, e2)), fmaxf(e3, e4));
            float c = __expf(m - mn);
            float p1 = __expf(e1 - mn), p2 = __expf(e2 - mn);
            float p3 = __expf(e3 - mn), p4 = __expf(e4 - mn);
            ssum = fmaf(ssum, c, (p1 + p2) + (p3 + p4));
            acc.x = fmaf(acc.x, c, fmaf(p1, v1.x, p2 * v2.x) + fmaf(p3, v3.x, p4 * v4.x));
            acc.y = fmaf(acc.y, c, fmaf(p1, v1.y, p2 * v2.y) + fmaf(p3, v3.y, p4 * v4.y));
            acc.z = fmaf(acc.z, c, fmaf(p1, v1.z, p2 * v2.z) + fmaf(p3, v3.z, p4 * v4.z));
            acc.w = fmaf(acc.w, c, fmaf(p1, v1.w, p2 * v2.w) + fmaf(p3, v3.w, p4 * v4.w));
            m = mn;
        }
        for (; u < cnt; ++u) {
            int s1 = __shfl_sync(0xffffffffu, mysrc, u);
            float4 v1 = ldh4(baseh, (size_t)s1 * 64 + lane);
            float e1 = warpSum(score128(v1, xr4, attk));
            float mn = fmaxf(m, e1);
            float c = __expf(m - mn), p = __expf(e1 - mn);
            ssum = fmaf(ssum, c, p);
            acc.x = fmaf(acc.x, c, p * v1.x);
            acc.y = fmaf(acc.y, c, p * v1.y);
            acc.z = fmaf(acc.z, c, p * v1.z);
            acc.w = fmaf(acc.w, c, p * v1.w);
            m = mn;
        }
    }
    float inv = 1.f / (ssum + 1e-16f);
    float4 o;
    o.x = acc.x * inv + bk.x; o.y = acc.y * inv + bk.y;
    o.z = acc.z * inv + bk.z; o.w = acc.w * inv + bk.w;
    o.x = o.x > 0.f ? o.x : expm1f(o.x);
    o.y = o.y > 0.f ? o.y : expm1f(o.y);
    o.z = o.z > 0.f ? o.z : expm1f(o.z);
    o.w = o.w > 0.f ? o.w : expm1f(o.w);
    reinterpret_cast<float4*>(g_h2)[(size_t)warp * 32 + lane] = o;
}

// mu/logstd layers: one warp per (node, head). head 0 = mu, head 1 = logstd.
__global__ void k_gat_mh(const float* __restrict__ attm, const float* __restrict__ bm,
                         const float* __restrict__ attl, const float* __restrict__ bl,
                         float* __restrict__ outmu, float* __restrict__ outls, int N) {
    int gw = (blockIdx.x * blockDim.x + threadIdx.x) >> 5;
    int lane = threadIdx.x & 31;
    int node = gw >> 1, head = gw & 1;
    if (node >= N) return;
    const float* att = head ? attl : attm;
    const float* bia = head ? bl : bm;
    float* outp = head ? outls : outmu;
    int off = head * 64;
    float attk = att[lane];
    float bk = bia[lane];
    const float* xin = g_c3out;
    float xrk = xin[(size_t)node * 128 + off + 32 + lane];
    float xlk0 = xin[(size_t)node * 128 + off + lane];
    float m = warpSum(lk(xlk0 + xrk) * attk);
    float ssum = 1.f, acc = xlk0;
    int beg = g_rowptr[node], end = g_rowptr[node + 1];
    for (int j0 = beg; j0 < end; j0 += 32) {
        int mysrc = (j0 + lane < end) ? g_srcs[j0 + lane] : 0;
        int cnt = min(32, end - j0);
        int u = 0;
        for (; u + 3 < cnt; u += 4) {
            int s1 = __shfl_sync(0xffffffffu, mysrc, u);
            int s2 = __shfl_sync(0xffffffffu, mysrc, u + 1);
            int s3 = __shfl_sync(0xffffffffu, mysrc, u + 2);
            int s4 = __shfl_sync(0xffffffffu, mysrc, u + 3);
            float v1 = xin[(size_t)s1 * 128 + off + lane];
            float v2 = xin[(size_t)s2 * 128 + off + lane];
            float v3 = xin[(size_t)s3 * 128 + off + lane];
            float v4 = xin[(size_t)s4 * 128 + off + lane];
            float e1 = warpSum(lk(v1 + xrk) * attk);
            float e2 = warpSum(lk(v2 + xrk) * attk);
            float e3 = warpSum(lk(v3 + xrk) * attk);
            float e4 = warpSum(lk(v4 + xrk) * attk);
            float mn = fmaxf(fmaxf(m, fmaxf(e1, e2)), fmaxf(e3, e4));
            float c = __expf(m - mn);
            float p1 = __expf(e1 - mn), p2 = __expf(e2 - mn);
            float p3 = __expf(e3 - mn), p4 = __expf(e4 - mn);
            ssum = fmaf(ssum, c, (p1 + p2) + (p3 + p4));
            acc = fmaf(acc, c, fmaf(p1, v1, p2 * v2) + fmaf(p3, v3, p4 * v4));
            m = mn;
        }
        for (; u < cnt; ++u) {
            int s1 = __shfl_sync(0xffffffffu, mysrc, u);
            float v1 = xin[(size_t)s1 * 128 + off + lane];
            float e1 = warpSum(lk(v1 + xrk) * attk);
            float mn = fmaxf(m, e1);
            float c = __expf(m - mn), p = __expf(e1 - mn);
            ssum = fmaf(ssum, c, p);
            acc = fmaf(acc, c, p * v1);
            m = mn;
        }
    }
    outp[(size_t)node * 32 + lane] = acc / (ssum + 1e-16f) + bk;
}

// ---------------- threefry + normal + z ----------------
__device__ __forceinline__ uint32_t rotl32(uint32_t v, int r) {
    return (v << r) | (v >> (32 - r));
}

__device__ __forceinline__ void threefry2x32(uint32_t k0, uint32_t k1,
                                             uint32_t& x0, uint32_t& x1) {
    uint32_t ks0 = k0, ks1 = k1, ks2 = k0 ^ k1 ^ 0x1BD11BDAu;
    x0 += ks0; x1 += ks1;
#define RND(r) { x0 += x1; x1 = rotl32(x1, r); x1 ^= x0; }
    RND(13) RND(15) RND(26) RND(6)   x0 += ks1; x1 += ks2 + 1u;
    RND(17) RND(29) RND(16) RND(24)  x0 += ks2; x1 += ks0 + 2u;
    RND(13) RND(15) RND(26) RND(6)   x0 += ks0; x1 += ks1 + 3u;
    RND(17) RND(29) RND(16) RND(24)  x0 += ks1; x1 += ks2 + 4u;
    RND(13) RND(15) RND(26) RND(6)   x0 += ks2; x1 += ks0 + 5u;
#undef RND
}

__device__ __forceinline__ float bits_to_normal(uint32_t bits) {
    float f = __uint_as_float((bits >> 9) | 0x3f800000u) - 1.0f;  // [0,1)
    const float lo = -0.99999994f;
    const float range = 2.0f;
    float u = fmaf(f, range, lo);
    u = fmaxf(u, lo);
    return 1.41421356f * erfinvf(u);
}

// JAX threefry_partitionable: (o0,o1)=threefry2x32(key, 0, i); draw = o0 ^ o1.
__global__ void k_z(float* __restrict__ out, int N) {
    int t = blockIdx.x * blockDim.x + threadIdx.x;
    int T = N * 32;
    if (t >= T) return;
    uint32_t x0 = 0u, x1 = (uint32_t)t;
    threefry2x32(0u, 1u, x0, x1);
    float n = bits_to_normal(x0 ^ x1);
    const float* mu = out;
    const float* ls = out + (size_t)N * 32;
    float* z = out + (size_t)2 * N * 32;
    z[t] = fmaf(n, expf(ls[t]), mu[t]);
}

// ---------------- launch ----------------
extern "C" void kernel_launch(void* const* d_in, const int* in_sizes, int n_in,
                              void* d_out, int out_size) {
    const float* x = (const float*)d_in[0];
    const void* ei = d_in[1];
    const float* Wl_c1 = (const float*)d_in[2];
    const float* Wr_c1 = (const float*)d_in[3];
    const float* att_c1 = (const float*)d_in[4];
    const float* b_c1 = (const float*)d_in[5];
    const float* Wl_c2 = (const float*)d_in[6];
    const float* Wr_c2 = (const float*)d_in[7];
    const float* att_c2 = (const float*)d_in[8];
    const float* b_c2 = (const float*)d_in[9];
    const float* Wl_mu = (const float*)d_in[10];
    const float* Wr_mu = (const float*)d_in[11];
    const float* att_mu = (const float*)d_in[12];
    const float* b_mu = (const float*)d_in[13];
    const float* Wl_ls = (const float*)d_in[14];
    const float* Wr_ls = (const float*)d_in[15];
    const float* att_ls = (const float*)d_in[16];
    const float* b_ls = (const float*)d_in[17];

    const int N = in_sizes[0] / 512;
    const int E = in_sizes[1] / 2;
    float* out = (float*)d_out;

    // ---- prologue ordered so the ncu capture slot (4th launch) hits k_sgemm<0> ----
    k_pack2<<<(512 * 32 + 255) / 256, 256>>>(Wl_c1, Wr_c1, 512, 32);   // 1
    k_zero2<<<(N + 255) / 256, 256>>>(N);                               // 2
    k_probe<<<1, 32>>>((const unsigned int*)ei);                        // 3
    {
        dim3 g((N + 127) / 128, 1);
        k_sgemm<0><<<g, 256>>>(x, N, 64, 512);                          // 4 <-- profiled
    }

    // ---- CSR build (by dst) ----
    k_hist<<<(E + 255) / 256, 256>>>(ei, E, N);
    int nb = (N + 1023) / 1024;
    k_scan1<<<nb, 1024>>>(N);
    k_scan2<<<1, 32>>>(nb);
    k_scan3<<<(N + 255) / 256, 256>>>(N, E);
    k_scatter<<<(E + 255) / 256, 256>>>(ei, E, N);

    // ---- layer c1 edge pass ----
    k_gat32<<<(N * 32 + 255) / 256, 256>>>(att_c1, b_c1, N);

    // ---- layer c2: 32 -> 128 (fp16 output table) ----
    k_pack2<<<(32 * 128 + 255) / 256, 256>>>(Wl_c2, Wr_c2, 32, 128);
    {
        dim3 g((N + 127) / 128, 4);
        k_sgemm<1><<<g, 256>>>(nullptr, N, 256, 32);
    }
    k_gat128<<<(N * 32 + 255) / 256, 256>>>(att_c2, b_c2, N);

    // ---- layers mu / logstd: 128 -> 32, one warp per (node, head) ----
    k_pack4<<<(128 * 32 + 255) / 256, 256>>>(Wl_mu, Wr_mu, Wl_ls, Wr_ls, 128);
    {
        dim3 g((N + 127) / 128, 2);
        k_sgemm<2><<<g, 256>>>(nullptr, N, 128, 128);
    }
    k_gat_mh<<<(N * 64 + 255) / 256, 256>>>(att_mu, b_mu, att_ls, b_ls,
                                            out, out + (size_t)N * 32, N);

    // ---- reparameterize: z = eps * exp(logstd) + mu ----
    k_z<<<(N * 32 + 255) / 256, 256>>>(out, N);
}

// round 15
// speedup vs baseline: 1.3254x; 1.0992x over previous
#include <cuda_runtime.h>
#include <cuda_fp16.h>
#include <stdint.h>

// ---------------- static scratch (no runtime alloc allowed) ----------------
#define MAXN 100000
#define MAXE 3200000

__device__ __align__(16) float g_c1out[MAXN * 64];          // [N, 64]  xl_c1 | xr_c1
__device__ __align__(16) float g_h1[MAXN * 32];             // [N, 32]
__device__ __align__(16) __half g_c2h[(size_t)MAXN * 256];  // [N,256] fp16 xl_c2 | xr_c2
__device__ __align__(16) float g_h2[MAXN * 128];            // [N,128]
__device__ __align__(16) float g_c3out[MAXN * 128];         // [N,128] mu_l|mu_r|ls_l|ls_r
__device__ __align__(16) float g_Wpack[512 * 64];           // packed weights (reused)
__device__ int g_counts[MAXN];
__device__ int g_fill[MAXN];
__device__ int g_rowptr[MAXN + 1];
__device__ int g_srcs[MAXE];
__device__ int g_blockSums[256];
__device__ int g_isI64;

// ---------------- helpers ----------------
__device__ __forceinline__ float warpSum(float v) {
#pragma unroll
    for (int o = 16; o > 0; o >>= 1) v += __shfl_xor_sync(0xffffffffu, v, o);
    return v;
}

__device__ __forceinline__ float lk(float v) { return v > 0.f ? v : 0.2f * v; }

// 8-lane-group sum (groups are lanes with equal lane>>3)
__device__ __forceinline__ float grpSum8(float v) {
    v += __shfl_xor_sync(0xffffffffu, v, 4);
    v += __shfl_xor_sync(0xffffffffu, v, 2);
    v += __shfl_xor_sync(0xffffffffu, v, 1);
    return v;
}

// packed fp32x2 FMA (sm_103a FFMA2) — IEEE fp32 per lane
__device__ __forceinline__ unsigned long long ffma2(unsigned long long a,
                                                    unsigned long long b,
                                                    unsigned long long c) {
    unsigned long long d;
    asm("fma.rn.f32x2 %0, %1, %2, %3;" : "=l"(d) : "l"(a), "l"(b), "l"(c));
    return d;
}
__device__ __forceinline__ unsigned long long pack2(float lo, float hi) {
    unsigned long long r;
    asm("mov.b64 %0, {%1, %2};" : "=l"(r) : "f"(lo), "f"(hi));
    return r;
}
__device__ __forceinline__ void unpack2(unsigned long long v, float& lo, float& hi) {
    asm("mov.b64 {%0, %1}, %2;" : "=f"(lo), "=f"(hi) : "l"(v));
}

// load 4 halves (8B) and widen to float4
__device__ __forceinline__ float4 ldh4(const uint2* __restrict__ p, size_t idx) {
    uint2 r = p[idx];
    __half2 a = *reinterpret_cast<__half2*>(&r.x);
    __half2 b = *reinterpret_cast<__half2*>(&r.y);
    float2 fa = __half22float2(a), fb = __half22float2(b);
    return make_float4(fa.x, fa.y, fb.x, fb.y);
}

__device__ __forceinline__ float dot4_lk(float4 v, float4 xr, float4 a) {
    return lk(v.x + xr.x) * a.x + lk(v.y + xr.y) * a.y +
           lk(v.z + xr.z) * a.z + lk(v.w + xr.w) * a.w;
}

// dtype-aware edge-index accessor (int32 vs int64 decided at runtime on device)
__device__ __forceinline__ int edgeIdx(const void* p, long long i) {
    if (g_isI64) return (int)((const long long*)p)[i];
    return ((const int*)p)[i];
}

// ---------------- dtype probe ----------------
__global__ void k_probe(const unsigned int* __restrict__ w) {
    if (threadIdx.x == 0 && blockIdx.x == 0) {
        int allz = 1;
        for (int i = 0; i < 32; i++) allz &= (w[2 * i + 1] == 0u);
        g_isI64 = allz;
    }
}

// ---------------- CSR build ----------------
__global__ void k_zero2(int n) {
    int i = blockIdx.x * blockDim.x + threadIdx.x;
    if (i < n) { g_counts[i] = 0; g_fill[i] = 0; }
}

__global__ void k_hist(const void* __restrict__ ei, int E, int N) {
    int e = blockIdx.x * blockDim.x + threadIdx.x;
    if (e < E) {
        int d = edgeIdx(ei, (long long)E + e);
        if ((unsigned)d < (unsigned)N) atomicAdd(&g_counts[d], 1);
    }
}

__global__ void k_scan1(int n) {  // block=1024
    __shared__ int sm[1024];
    int tid = threadIdx.x;
    int i = blockIdx.x * 1024 + tid;
    int v = (i < n) ? g_counts[i] : 0;
    sm[tid] = v;
    __syncthreads();
#pragma unroll
    for (int off = 1; off < 1024; off <<= 1) {
        int add = (tid >= off) ? sm[tid - off] : 0;
        __syncthreads();
        sm[tid] += add;
        __syncthreads();
    }
    if (i < n) g_rowptr[i] = sm[tid] - v;
    if (tid == 1023) g_blockSums[blockIdx.x] = sm[1023];
}

__global__ void k_scan2(int nb) {
    if (threadIdx.x == 0 && blockIdx.x == 0) {
        int run = 0;
        for (int b = 0; b < nb; b++) { int t = g_blockSums[b]; g_blockSums[b] = run; run += t; }
    }
}

__global__ void k_scan3(int n, int E) {
    int i = blockIdx.x * blockDim.x + threadIdx.x;
    if (i < n) g_rowptr[i] += g_blockSums[i >> 10];
    if (i == 0) g_rowptr[n] = E;
}

__global__ void k_scatter(const void* __restrict__ ei, int E, int N) {
    int e = blockIdx.x * blockDim.x + threadIdx.x;
    if (e < E) {
        int d = edgeIdx(ei, (long long)E + e);
        int s = edgeIdx(ei, e);
        if ((unsigned)d < (unsigned)N && (unsigned)s < (unsigned)N) {
            int p = g_rowptr[d] + atomicAdd(&g_fill[d], 1);
            g_srcs[p] = s;
        }
    }
}

// ---------------- weight packing ----------------
__global__ void k_pack2(const float* __restrict__ Wl, const float* __restrict__ Wr,
                        int K, int D) {
    int i = blockIdx.x * blockDim.x + threadIdx.x;
    if (i >= K * D) return;
    int k = i / D, d = i % D;
    g_Wpack[k * 2 * D + d]     = Wl[i];
    g_Wpack[k * 2 * D + D + d] = Wr[i];
}

__global__ void k_pack4(const float* __restrict__ W0, const float* __restrict__ W1,
                        const float* __restrict__ W2, const float* __restrict__ W3,
                        int K) {
    int i = blockIdx.x * blockDim.x + threadIdx.x;
    if (i >= K * 32) return;
    int k = i / 32, d = i % 32;
    g_Wpack[k * 128 + d]       = W0[i];
    g_Wpack[k * 128 + 32 + d]  = W1[i];
    g_Wpack[k * 128 + 64 + d]  = W2[i];
    g_Wpack[k * 128 + 96 + d]  = W3[i];
}

// ---------------- SGEMM (R13: double-buffered, 8x4 tile, FFMA2) ----------------
// LAYER 1 stores its output as fp16 into g_c2h.
template <int LAYER>
__global__ __launch_bounds__(256, 3) void k_sgemm(const float* __restrict__ Aext,
                                                  int M, int Nn, int K) {
    const float* __restrict__ A = (LAYER == 0) ? Aext : (LAYER == 1 ? g_h1 : g_h2);
    float* __restrict__ C = (LAYER == 0) ? g_c1out : (LAYER == 1 ? nullptr : g_c3out);
    const float* __restrict__ B = g_Wpack;

    __shared__ float As[2][16][128];
    __shared__ float Bs[2][16][64];
    const int rowBase = blockIdx.x * 128;
    const int colBase = blockIdx.y * 64;
    const int t = threadIdx.x;
    const int tx = t & 15;
    const int ty = t >> 4;

    const int rA0 = (t) >> 2, cA0 = (t) & 3;
    const int rA1 = (t + 256) >> 2, cA1 = (t + 256) & 3;
    const int kkB = t >> 4, cB = t & 15;

    unsigned long long acc2[4][4];
#pragma unroll
    for (int i = 0; i < 4; i++)
#pragma unroll
        for (int j = 0; j < 4; j++) acc2[i][j] = 0ull;

    float4 aV0 = make_float4(0.f, 0.f, 0.f, 0.f), aV1 = aV0, bV;
    {
        int g0 = rowBase + rA0, g1 = rowBase + rA1;
        if (g0 < M) aV0 = *reinterpret_cast<const float4*>(A + (size_t)g0 * K + cA0 * 4);
        if (g1 < M) aV1 = *reinterpret_cast<const float4*>(A + (size_t)g1 * K + cA1 * 4);
        bV = *reinterpret_cast<const float4*>(B + (size_t)kkB * Nn + colBase + cB * 4);
    }
    As[0][cA0 * 4 + 0][rA0] = aV0.x; As[0][cA0 * 4 + 1][rA0] = aV0.y;
    As[0][cA0 * 4 + 2][rA0] = aV0.z; As[0][cA0 * 4 + 3][rA0] = aV0.w;
    As[0][cA1 * 4 + 0][rA1] = aV1.x; As[0][cA1 * 4 + 1][rA1] = aV1.y;
    As[0][cA1 * 4 + 2][rA1] = aV1.z; As[0][cA1 * 4 + 3][rA1] = aV1.w;
    *reinterpret_cast<float4*>(&Bs[0][kkB][cB * 4]) = bV;
    __syncthreads();

    const int nIter = K >> 4;
    int cur = 0;
    for (int it = 0; it < nIter; ++it) {
        float4 aN0, aN1, bN;
        bool havNext = (it + 1 < nIter);
        if (havNext) {
            int k0n = (it + 1) << 4;
            int g0 = rowBase + rA0, g1 = rowBase + rA1;
            aN0 = make_float4(0.f, 0.f, 0.f, 0.f); aN1 = aN0;
            if (g0 < M) aN0 = *reinterpret_cast<const float4*>(A + (size_t)g0 * K + k0n + cA0 * 4);
            if (g1 < M) aN1 = *reinterpret_cast<const float4*>(A + (size_t)g1 * K + k0n + cA1 * 4);
            bN = *reinterpret_cast<const float4*>(B + (size_t)(k0n + kkB) * Nn + colBase + cB * 4);
        }
#pragma unroll
        for (int k = 0; k < 16; k++) {
            unsigned long long a2[4];
#pragma unroll
            for (int i = 0; i < 4; i++)
                a2[i] = *reinterpret_cast<const unsigned long long*>(&As[cur][k][ty * 8 + i * 2]);
            unsigned long long bd[4];
#pragma unroll
            for (int j = 0; j < 4; j++) {
                float bj = Bs[cur][k][tx * 4 + j];
                bd[j] = pack2(bj, bj);
            }
#pragma unroll
            for (int i = 0; i < 4; i++)
#pragma unroll
                for (int j = 0; j < 4; j++) acc2[i][j] = ffma2(a2[i], bd[j], acc2[i][j]);
        }
        if (havNext) {
            int nxt = cur ^ 1;
            As[nxt][cA0 * 4 + 0][rA0] = aN0.x; As[nxt][cA0 * 4 + 1][rA0] = aN0.y;
            As[nxt][cA0 * 4 + 2][rA0] = aN0.z; As[nxt][cA0 * 4 + 3][rA0] = aN0.w;
            As[nxt][cA1 * 4 + 0][rA1] = aN1.x; As[nxt][cA1 * 4 + 1][rA1] = aN1.y;
            As[nxt][cA1 * 4 + 2][rA1] = aN1.z; As[nxt][cA1 * 4 + 3][rA1] = aN1.w;
            *reinterpret_cast<float4*>(&Bs[nxt][kkB][cB * 4]) = bN;
            __syncthreads();
        }
        cur ^= 1;
    }
#pragma unroll
    for (int i = 0; i < 4; i++) {
        float lo[4], hi[4];
#pragma unroll
        for (int j = 0; j < 4; j++) unpack2(acc2[i][j], lo[j], hi[j]);
        int r0 = rowBase + ty * 8 + i * 2;
        if (LAYER == 1) {
            if (r0 < M) {
                __half2 h01 = __floats2half2_rn(lo[0], lo[1]);
                __half2 h23 = __floats2half2_rn(lo[2], lo[3]);
                uint2 r; r.x = *reinterpret_cast<unsigned*>(&h01); r.y = *reinterpret_cast<unsigned*>(&h23);
                *reinterpret_cast<uint2*>(&g_c2h[(size_t)r0 * Nn + colBase + tx * 4]) = r;
            }
            if (r0 + 1 < M) {
                __half2 h01 = __floats2half2_rn(hi[0], hi[1]);
                __half2 h23 = __floats2half2_rn(hi[2], hi[3]);
                uint2 r; r.x = *reinterpret_cast<unsigned*>(&h01); r.y = *reinterpret_cast<unsigned*>(&h23);
                *reinterpret_cast<uint2*>(&g_c2h[(size_t)(r0 + 1) * Nn + colBase + tx * 4]) = r;
            }
        } else {
            if (r0 < M)
                *reinterpret_cast<float4*>(C + (size_t)r0 * Nn + colBase + tx * 4) =
                    make_float4(lo[0], lo[1], lo[2], lo[3]);
            if (r0 + 1 < M)
                *reinterpret_cast<float4*>(C + (size_t)(r0 + 1) * Nn + colBase + tx * 4) =
                    make_float4(hi[0], hi[1], hi[2], hi[3]);
        }
    }
}

// ---------------- GATv2 edge kernels ----------------
// d=32 layer 1: 8-lane groups, 4 edges in flight per warp, group-local online softmax.
__global__ void k_gat32(const float* __restrict__ att, const float* __restrict__ bias, int N) {
    int warp = (blockIdx.x * blockDim.x + threadIdx.x) >> 5;
    int lane = threadIdx.x & 31;
    if (warp >= N) return;
    int q = lane & 7, g = lane >> 3;
    const float* xin = g_c1out;
    float4 attq = *reinterpret_cast<const float4*>(att + q * 4);
    float4 xrq = *reinterpret_cast<const float4*>(xin + (size_t)warp * 64 + 32 + q * 4);
    float4 xlq = *reinterpret_cast<const float4*>(xin + (size_t)warp * 64 + q * 4);

    // self-loop seeds group 0
    float m, s;
    float4 acc;
    {
        float sc = grpSum8(dot4_lk(xlq, xrq, attq));
        if (g == 0) { m = sc; s = 1.f; acc = xlq; }
        else { m = -1e30f; s = 0.f; acc = make_float4(0.f, 0.f, 0.f, 0.f); }
    }
    int beg = g_rowptr[warp], end = g_rowptr[warp + 1];
    for (int j0 = beg; j0 < end; j0 += 32) {
        int cnt = min(32, end - j0);
        int mysrc = (lane < cnt) ? g_srcs[j0 + lane] : 0;
        for (int k = 0; k * 4 < cnt; ++k) {
            int u = k * 4 + g;                       // group-uniform
            int src = __shfl_sync(0xffffffffu, mysrc, u & 31);
            float4 v = make_float4(0.f, 0.f, 0.f, 0.f);
            if (u < cnt)
                v = *reinterpret_cast<const float4*>(xin + (size_t)src * 64 + q * 4);
            float sc = grpSum8(dot4_lk(v, xrq, attq));
            if (u < cnt) {                           // group-uniform branch
                float mn = fmaxf(m, sc);
                float c = __expf(m - mn), p = __expf(sc - mn);
                s = fmaf(s, c, p);
                acc.x = fmaf(acc.x, c, p * v.x);
                acc.y = fmaf(acc.y, c, p * v.y);
                acc.z = fmaf(acc.z, c, p * v.z);
                acc.w = fmaf(acc.w, c, p * v.w);
                m = mn;
            }
        }
    }
    // merge 4 group streams
    float mo = fmaxf(m, __shfl_xor_sync(0xffffffffu, m, 8));
    mo = fmaxf(mo, __shfl_xor_sync(0xffffffffu, mo, 16));
    float scl = __expf(m - mo);
    float ss = s * scl;
    ss += __shfl_xor_sync(0xffffffffu, ss, 8);
    ss += __shfl_xor_sync(0xffffffffu, ss, 16);
    float4 a;
    a.x = acc.x * scl; a.y = acc.y * scl; a.z = acc.z * scl; a.w = acc.w * scl;
    a.x += __shfl_xor_sync(0xffffffffu, a.x, 8);  a.x += __shfl_xor_sync(0xffffffffu, a.x, 16);
    a.y += __shfl_xor_sync(0xffffffffu, a.y, 8);  a.y += __shfl_xor_sync(0xffffffffu, a.y, 16);
    a.z += __shfl_xor_sync(0xffffffffu, a.z, 8);  a.z += __shfl_xor_sync(0xffffffffu, a.z, 16);
    a.w += __shfl_xor_sync(0xffffffffu, a.w, 8);  a.w += __shfl_xor_sync(0xffffffffu, a.w, 16);
    if (g == 0) {
        float4 bq = *reinterpret_cast<const float4*>(bias + q * 4);
        float inv = 1.f / (ss + 1e-16f);
        float4 o;
        o.x = a.x * inv + bq.x; o.y = a.y * inv + bq.y;
        o.z = a.z * inv + bq.z; o.w = a.w * inv + bq.w;
        o.x = o.x > 0.f ? o.x : expm1f(o.x);
        o.y = o.y > 0.f ? o.y : expm1f(o.y);
        o.z = o.z > 0.f ? o.z : expm1f(o.z);
        o.w = o.w > 0.f ? o.w : expm1f(o.w);
        *reinterpret_cast<float4*>(g_h1 + (size_t)warp * 32 + q * 4) = o;
    }
}

__device__ __forceinline__ float score128(float4 v, float4 xr, float4 a) {
    return lk(v.x + xr.x) * a.x + lk(v.y + xr.y) * a.y +
           lk(v.z + xr.z) * a.z + lk(v.w + xr.w) * a.w;
}

// layer-2 edge pass (R14 version): fp16 gathers, warp-wide online softmax, 4-edge unroll.
__global__ void k_gat128(const float* __restrict__ att, const float* __restrict__ bias, int N) {
    int warp = (blockIdx.x * blockDim.x + threadIdx.x) >> 5;
    int lane = threadIdx.x & 31;
    if (warp >= N) return;
    const uint2* baseh = reinterpret_cast<const uint2*>(g_c2h);
    float4 attk = reinterpret_cast<const float4*>(att)[lane];
    float4 bk = reinterpret_cast<const float4*>(bias)[lane];
    float4 xr4 = ldh4(baseh, (size_t)warp * 64 + 32 + lane);
    float4 xl4 = ldh4(baseh, (size_t)warp * 64 + lane);
    float m = warpSum(score128(xl4, xr4, attk));
    float ssum = 1.f;
    float4 acc = xl4;
    int beg = g_rowptr[warp], end = g_rowptr[warp + 1];
    for (int j0 = beg; j0 < end; j0 += 32) {
        int mysrc = (j0 + lane < end) ? g_srcs[j0 + lane] : 0;
        int cnt = min(32, end - j0);
        int u = 0;
        for (; u + 3 < cnt; u += 4) {
            int s1 = __shfl_sync(0xffffffffu, mysrc, u);
            int s2 = __shfl_sync(0xffffffffu, mysrc, u + 1);
            int s3 = __shfl_sync(0xffffffffu, mysrc, u + 2);
            int s4 = __shfl_sync(0xffffffffu, mysrc, u + 3);
            float4 v1 = ldh4(baseh, (size_t)s1 * 64 + lane);
            float4 v2 = ldh4(baseh, (size_t)s2 * 64 + lane);
            float4 v3 = ldh4(baseh, (size_t)s3 * 64 + lane);
            float4 v4 = ldh4(baseh, (size_t)s4 * 64 + lane);
            float e1 = warpSum(score128(v1, xr4, attk));
            float e2 = warpSum(score128(v2, xr4, attk));
            float e3 = warpSum(score128(v3, xr4, attk));
            float e4 = warpSum(score128(v4, xr4, attk));
            float mn = fmaxf(fmaxf(m, fmaxf(e1, e2)), fmaxf(e3, e4));
            float c = __expf(m - mn);
            float p1 = __expf(e1 - mn), p2 = __expf(e2 - mn);
            float p3 = __expf(e3 - mn), p4 = __expf(e4 - mn);
            ssum = fmaf(ssum, c, (p1 + p2) + (p3 + p4));
            acc.x = fmaf(acc.x, c, fmaf(p1, v1.x, p2 * v2.x) + fmaf(p3, v3.x, p4 * v4.x));
            acc.y = fmaf(acc.y, c, fmaf(p1, v1.y, p2 * v2.y) + fmaf(p3, v3.y, p4 * v4.y));
            acc.z = fmaf(acc.z, c, fmaf(p1, v1.z, p2 * v2.z) + fmaf(p3, v3.z, p4 * v4.z));
            acc.w = fmaf(acc.w, c, fmaf(p1, v1.w, p2 * v2.w) + fmaf(p3, v3.w, p4 * v4.w));
            m = mn;
        }
        for (; u < cnt; ++u) {
            int s1 = __shfl_sync(0xffffffffu, mysrc, u);
            float4 v1 = ldh4(baseh, (size_t)s1 * 64 + lane);
            float e1 = warpSum(score128(v1, xr4, attk));
            float mn = fmaxf(m, e1);
            float c = __expf(m - mn), p = __expf(e1 - mn);
            ssum = fmaf(ssum, c, p);
            acc.x = fmaf(acc.x, c, p * v1.x);
            acc.y = fmaf(acc.y, c, p * v1.y);
            acc.z = fmaf(acc.z, c, p * v1.z);
            acc.w = fmaf(acc.w, c, p * v1.w);
            m = mn;
        }
    }
    float inv = 1.f / (ssum + 1e-16f);
    float4 o;
    o.x = acc.x * inv + bk.x; o.y = acc.y * inv + bk.y;
    o.z = acc.z * inv + bk.z; o.w = acc.w * inv + bk.w;
    o.x = o.x > 0.f ? o.x : expm1f(o.x);
    o.y = o.y > 0.f ? o.y : expm1f(o.y);
    o.z = o.z > 0.f ? o.z : expm1f(o.z);
    o.w = o.w > 0.f ? o.w : expm1f(o.w);
    reinterpret_cast<float4*>(g_h2)[(size_t)warp * 32 + lane] = o;
}

// mu/logstd layers: one warp per (node, head), 8-lane groups, 4 edges in flight.
__global__ void k_gat_mh(const float* __restrict__ attm, const float* __restrict__ bm,
                         const float* __restrict__ attl, const float* __restrict__ bl,
                         float* __restrict__ outmu, float* __restrict__ outls, int N) {
    int gw = (blockIdx.x * blockDim.x + threadIdx.x) >> 5;
    int lane = threadIdx.x & 31;
    int node = gw >> 1, head = gw & 1;
    if (node >= N) return;
    int q = lane & 7, g = lane >> 3;
    const float* att = head ? attl : attm;
    const float* bia = head ? bl : bm;
    float* outp = head ? outls : outmu;
    int off = head * 64;
    const float* xin = g_c3out;
    float4 attq = *reinterpret_cast<const float4*>(att + q * 4);
    float4 xrq = *reinterpret_cast<const float4*>(xin + (size_t)node * 128 + off + 32 + q * 4);
    float4 xlq = *reinterpret_cast<const float4*>(xin + (size_t)node * 128 + off + q * 4);

    float m, s;
    float4 acc;
    {
        float sc = grpSum8(dot4_lk(xlq, xrq, attq));
        if (g == 0) { m = sc; s = 1.f; acc = xlq; }
        else { m = -1e30f; s = 0.f; acc = make_float4(0.f, 0.f, 0.f, 0.f); }
    }
    int beg = g_rowptr[node], end = g_rowptr[node + 1];
    for (int j0 = beg; j0 < end; j0 += 32) {
        int cnt = min(32, end - j0);
        int mysrc = (lane < cnt) ? g_srcs[j0 + lane] : 0;
        for (int k = 0; k * 4 < cnt; ++k) {
            int u = k * 4 + g;
            int src = __shfl_sync(0xffffffffu, mysrc, u & 31);
            float4 v = make_float4(0.f, 0.f, 0.f, 0.f);
            if (u < cnt)
                v = *reinterpret_cast<const float4*>(xin + (size_t)src * 128 + off + q * 4);
            float sc = grpSum8(dot4_lk(v, xrq, attq));
            if (u < cnt) {
                float mn = fmaxf(m, sc);
                float c = __expf(m - mn), p = __expf(sc - mn);
                s = fmaf(s, c, p);
                acc.x = fmaf(acc.x, c, p * v.x);
                acc.y = fmaf(acc.y, c, p * v.y);
                acc.z = fmaf(acc.z, c, p * v.z);
                acc.w = fmaf(acc.w, c, p * v.w);
                m = mn;
            }
        }
    }
    float mo = fmaxf(m, __shfl_xor_sync(0xffffffffu, m, 8));
    mo = fmaxf(mo, __shfl_xor_sync(0xffffffffu, mo, 16));
    float scl = __expf(m - mo);
    float ss = s * scl;
    ss += __shfl_xor_sync(0xffffffffu, ss, 8);
    ss += __shfl_xor_sync(0xffffffffu, ss, 16);
    float4 a;
    a.x = acc.x * scl; a.y = acc.y * scl; a.z = acc.z * scl; a.w = acc.w * scl;
    a.x += __shfl_xor_sync(0xffffffffu, a.x, 8);  a.x += __shfl_xor_sync(0xffffffffu, a.x, 16);
    a.y += __shfl_xor_sync(0xffffffffu, a.y, 8);  a.y += __shfl_xor_sync(0xffffffffu, a.y, 16);
    a.z += __shfl_xor_sync(0xffffffffu, a.z, 8);  a.z += __shfl_xor_sync(0xffffffffu, a.z, 16);
    a.w += __shfl_xor_sync(0xffffffffu, a.w, 8);  a.w += __shfl_xor_sync(0xffffffffu, a.w, 16);
    if (g == 0) {
        float4 bq = *reinterpret_cast<const float4*>(bia + q * 4);
        float inv = 1.f / (ss + 1e-16f);
        float4 o;
        o.x = a.x * inv + bq.x; o.y = a.y * inv + bq.y;
        o.z = a.z * inv + bq.z; o.w = a.w * inv + bq.w;
        *reinterpret_cast<float4*>(outp + (size_t)node * 32 + q * 4) = o;
    }
}

// ---------------- threefry + normal + z ----------------
__device__ __forceinline__ uint32_t rotl32(uint32_t v, int r) {
    return (v << r) | (v >> (32 - r));
}

__device__ __forceinline__ void threefry2x32(uint32_t k0, uint32_t k1,
                                             uint32_t& x0, uint32_t& x1) {
    uint32_t ks0 = k0, ks1 = k1, ks2 = k0 ^ k1 ^ 0x1BD11BDAu;
    x0 += ks0; x1 += ks1;
#define RND(r) { x0 += x1; x1 = rotl32(x1, r); x1 ^= x0; }
    RND(13) RND(15) RND(26) RND(6)   x0 += ks1; x1 += ks2 + 1u;
    RND(17) RND(29) RND(16) RND(24)  x0 += ks2; x1 += ks0 + 2u;
    RND(13) RND(15) RND(26) RND(6)   x0 += ks0; x1 += ks1 + 3u;
    RND(17) RND(29) RND(16) RND(24)  x0 += ks1; x1 += ks2 + 4u;
    RND(13) RND(15) RND(26) RND(6)   x0 += ks2; x1 += ks0 + 5u;
#undef RND
}

__device__ __forceinline__ float bits_to_normal(uint32_t bits) {
    float f = __uint_as_float((bits >> 9) | 0x3f800000u) - 1.0f;  // [0,1)
    const float lo = -0.99999994f;
    const float range = 2.0f;
    float u = fmaf(f, range, lo);
    u = fmaxf(u, lo);
    return 1.41421356f * erfinvf(u);
}

// JAX threefry_partitionable: (o0,o1)=threefry2x32(key, 0, i); draw = o0 ^ o1.
__global__ void k_z(float* __restrict__ out, int N) {
    int t = blockIdx.x * blockDim.x + threadIdx.x;
    int T = N * 32;
    if (t >= T) return;
    uint32_t x0 = 0u, x1 = (uint32_t)t;
    threefry2x32(0u, 1u, x0, x1);
    float n = bits_to_normal(x0 ^ x1);
    const float* mu = out;
    const float* ls = out + (size_t)N * 32;
    float* z = out + (size_t)2 * N * 32;
    z[t] = fmaf(n, expf(ls[t]), mu[t]);
}

// ---------------- launch ----------------
extern "C" void kernel_launch(void* const* d_in, const int* in_sizes, int n_in,
                              void* d_out, int out_size) {
    const float* x = (const float*)d_in[0];
    const void* ei = d_in[1];
    const float* Wl_c1 = (const float*)d_in[2];
    const float* Wr_c1 = (const float*)d_in[3];
    const float* att_c1 = (const float*)d_in[4];
    const float* b_c1 = (const float*)d_in[5];
    const float* Wl_c2 = (const float*)d_in[6];
    const float* Wr_c2 = (const float*)d_in[7];
    const float* att_c2 = (const float*)d_in[8];
    const float* b_c2 = (const float*)d_in[9];
    const float* Wl_mu = (const float*)d_in[10];
    const float* Wr_mu = (const float*)d_in[11];
    const float* att_mu = (const float*)d_in[12];
    const float* b_mu = (const float*)d_in[13];
    const float* Wl_ls = (const float*)d_in[14];
    const float* Wr_ls = (const float*)d_in[15];
    const float* att_ls = (const float*)d_in[16];
    const float* b_ls = (const float*)d_in[17];

    const int N = in_sizes[0] / 512;
    const int E = in_sizes[1] / 2;
    float* out = (float*)d_out;

    // ---- prologue ordered so the ncu capture slot (4th launch) hits k_sgemm<0> ----
    k_pack2<<<(512 * 32 + 255) / 256, 256>>>(Wl_c1, Wr_c1, 512, 32);   // 1
    k_zero2<<<(N + 255) / 256, 256>>>(N);                               // 2
    k_probe<<<1, 32>>>((const unsigned int*)ei);                        // 3
    {
        dim3 g((N + 127) / 128, 1);
        k_sgemm<0><<<g, 256>>>(x, N, 64, 512);                          // 4 <-- profiled
    }

    // ---- CSR build (by dst) ----
    k_hist<<<(E + 255) / 256, 256>>>(ei, E, N);
    int nb = (N + 1023) / 1024;
    k_scan1<<<nb, 1024>>>(N);
    k_scan2<<<1, 32>>>(nb);
    k_scan3<<<(N + 255) / 256, 256>>>(N, E);
    k_scatter<<<(E + 255) / 256, 256>>>(ei, E, N);

    // ---- layer c1 edge pass ----
    k_gat32<<<(N * 32 + 255) / 256, 256>>>(att_c1, b_c1, N);

    // ---- layer c2: 32 -> 128 (fp16 output table) ----
    k_pack2<<<(32 * 128 + 255) / 256, 256>>>(Wl_c2, Wr_c2, 32, 128);
    {
        dim3 g((N + 127) / 128, 4);
        k_sgemm<1><<<g, 256>>>(nullptr, N, 256, 32);
    }
    k_gat128<<<(N * 32 + 255) / 256, 256>>>(att_c2, b_c2, N);

    // ---- layers mu / logstd: 128 -> 32, one warp per (node, head) ----
    k_pack4<<<(128 * 32 + 255) / 256, 256>>>(Wl_mu, Wr_mu, Wl_ls, Wr_ls, 128);
    {
        dim3 g((N + 127) / 128, 2);
        k_sgemm<2><<<g, 256>>>(nullptr, N, 128, 128);
    }
    k_gat_mh<<<(N * 64 + 255) / 256, 256>>>(att_mu, b_mu, att_ls, b_ls,
                                            out, out + (size_t)N * 32, N);

    // ---- reparameterize: z = eps * exp(logstd) + mu ----
    k_z<<<(N * 32 + 255) / 256, 256>>>(out, N);
}